// round 15
// baseline (speedup 1.0000x reference)
#include <cuda_runtime.h>
#include <cuda_fp16.h>
#include <math.h>
#include <stdint.h>

#define BT    4096
#define DIMD  1024
#define NH    16
#define HD    64
#define TT    2048
#define MLPH  4096
#define QSTR  3072

// ---------------- scratch -------------------------------------------------------
__device__ __half g_h  [BT * DIMD];
__device__ __half g_a1 [BT * DIMD];
__device__ __half g_qkv[BT * QSTR];
__device__ __half g_ao [BT * DIMD];
__device__ __half g_ae [BT * DIMD];
__device__ __half g_hid[BT * MLPH];
__device__ float  g_x1 [BT * DIMD];
__device__ float  g_bqkv[QSTR];
// NATURAL layout ([K][N]) fp16 weights
__device__ __half g_wqkv[DIMD * QSTR];
__device__ __half g_wo  [DIMD * DIMD];
__device__ __half g_wae2[DIMD * DIMD];
__device__ __half g_wmod[DIMD * 2048];
__device__ __half g_wm1 [DIMD * MLPH];
__device__ __half g_wm2 [MLPH * DIMD];

// ---------------- fused weight convert ----------------------------------------------
#define U_QKV  786432
#define U_O    1048576
#define U_AE2  1310720
#define U_M1   2359296
#define U_M2   3407872
#define U_MOD  3670016
#define U_TOT  3670784

__global__ void conv_all_kernel(const float* __restrict__ q_w, const float* __restrict__ k_w,
                                const float* __restrict__ v_w, const float* __restrict__ o_w,
                                const float* __restrict__ ae2_w, const float* __restrict__ mod_w,
                                const float* __restrict__ m1_w, const float* __restrict__ m2_w,
                                const float* __restrict__ q_b, const float* __restrict__ k_b,
                                const float* __restrict__ v_b)
{
    int u = blockIdx.x * 256 + threadIdx.x;
    if (u < U_QKV) {
        int j = u >> 18, r = u & 262143;
        int k = r >> 8, n4 = (r & 255) << 2;
        const float* s = (j == 0) ? q_w : ((j == 1) ? k_w : v_w);
        float4 v = *(const float4*)&s[(size_t)k * 1024 + n4];
        uint2 o;
        ((__half2*)&o)[0] = __floats2half2_rn(v.x, v.y);
        ((__half2*)&o)[1] = __floats2half2_rn(v.z, v.w);
        *(uint2*)&g_wqkv[(size_t)k * QSTR + j * 1024 + n4] = o;
    } else if (u < U_O) {
        int e4 = (u - U_QKV) << 2;
        float4 v = *(const float4*)&o_w[e4];
        uint2 o;
        ((__half2*)&o)[0] = __floats2half2_rn(v.x, v.y);
        ((__half2*)&o)[1] = __floats2half2_rn(v.z, v.w);
        *(uint2*)&g_wo[e4] = o;
    } else if (u < U_AE2) {
        int e4 = (u - U_O) << 2;
        float4 v = *(const float4*)&ae2_w[e4];
        uint2 o;
        ((__half2*)&o)[0] = __floats2half2_rn(v.x, v.y);
        ((__half2*)&o)[1] = __floats2half2_rn(v.z, v.w);
        *(uint2*)&g_wae2[e4] = o;
    } else if (u < U_M1) {
        int e4 = (u - U_AE2) << 2;
        float4 v = *(const float4*)&m1_w[e4];
        uint2 o;
        ((__half2*)&o)[0] = __floats2half2_rn(v.x, v.y);
        ((__half2*)&o)[1] = __floats2half2_rn(v.z, v.w);
        *(uint2*)&g_wm1[e4] = o;
    } else if (u < U_M2) {
        int e4 = (u - U_M1) << 2;
        float4 v = *(const float4*)&m2_w[e4];
        uint2 o;
        ((__half2*)&o)[0] = __floats2half2_rn(v.x, v.y);
        ((__half2*)&o)[1] = __floats2half2_rn(v.z, v.w);
        *(uint2*)&g_wm2[e4] = o;
    } else if (u < U_MOD) {
        int r = u - U_M2;
        int k = r >> 8, j4 = (r & 255) << 2;
        float4 sh = *(const float4*)&mod_w[(size_t)k * 4096 + j4];
        float4 sc = *(const float4*)&mod_w[(size_t)k * 4096 + 1024 + j4];
        uint4 o;
        ((__half2*)&o)[0] = __floats2half2_rn(sh.x, sc.x);
        ((__half2*)&o)[1] = __floats2half2_rn(sh.y, sc.y);
        ((__half2*)&o)[2] = __floats2half2_rn(sh.z, sc.z);
        ((__half2*)&o)[3] = __floats2half2_rn(sh.w, sc.w);
        *(uint4*)&g_wmod[(size_t)k * 2048 + 2 * j4] = o;
    } else {
        int r = u - U_MOD;
        int i = r << 2;
        float4 v;
        if (i < 1024)      v = *(const float4*)&q_b[i];
        else if (i < 2048) v = *(const float4*)&k_b[i - 1024];
        else               v = *(const float4*)&v_b[i - 2048];
        *(float4*)&g_bqkv[i] = v;
    }
}

// ---------------- rmsnorm ------------------------------------------------------------
__global__ void rmsnorm_kernel(const float* __restrict__ x,
                               const float* __restrict__ w,
                               __half* __restrict__ y)
{
    int row = blockIdx.x;
    const float* xr = x + (size_t)row * DIMD;
    float v[4];
    float s = 0.f;
#pragma unroll
    for (int i = 0; i < 4; i++) {
        v[i] = xr[threadIdx.x + i * 256];
        s += v[i] * v[i];
    }
#pragma unroll
    for (int o = 16; o > 0; o >>= 1) s += __shfl_xor_sync(0xffffffffu, s, o);
    __shared__ float red[8];
    if ((threadIdx.x & 31) == 0) red[threadIdx.x >> 5] = s;
    __syncthreads();
    if (threadIdx.x == 0) {
        float t = 0.f;
#pragma unroll
        for (int i = 0; i < 8; i++) t += red[i];
        red[0] = rsqrtf(t * (1.0f / DIMD) + 1e-6f);
    }
    __syncthreads();
    float r = red[0];
    __half* yr = y + (size_t)row * DIMD;
#pragma unroll
    for (int i = 0; i < 4; i++) {
        int c = threadIdx.x + i * 256;
        yr[c] = __float2half_rn(v[i] * r * w[c]);
    }
}

// ---------------- per-head rmsnorm on qkv buffer --------------------------------------
__global__ void headnorm_kernel(__half* __restrict__ qkv,
                                const float* __restrict__ qw, const float* __restrict__ kw)
{
    int sel = blockIdx.y;
    const float* w = sel ? kw : qw;
    float scale = sel ? 1.0f : 0.125f;
    int gw   = (blockIdx.x * blockDim.x + threadIdx.x) >> 5;
    int lane = threadIdx.x & 31;
    if (gw >= BT * NH) return;
    int token = gw >> 4, head = gw & 15;
    __half* p = qkv + (size_t)token * QSTR + sel * 1024 + head * 64;
    float a = __half2float(p[lane]);
    float b = __half2float(p[lane + 32]);
    float s = a * a + b * b;
#pragma unroll
    for (int o = 16; o > 0; o >>= 1) s += __shfl_xor_sync(0xffffffffu, s, o);
    float r = rsqrtf(s * (1.0f / HD) + 1e-6f) * scale;
    p[lane]      = __float2half_rn(a * r * w[lane]);
    p[lane + 32] = __float2half_rn(b * r * w[lane + 32]);
}

// ---------------- ae1 (K=16) -----------------------------------------------------------
__global__ void __launch_bounds__(256) ae1_kernel(
    const float* __restrict__ A, const float* __restrict__ W,
    const float* __restrict__ bias, __half* __restrict__ C)
{
    __shared__ float Ws[16 * 256];
    __shared__ float As[32 * 16];
    int tid = threadIdx.x;
    int colbase = blockIdx.y * 256;
    for (int i = tid; i < 1024; i += 256) {
        int row = i >> 6, c4 = (i & 63) << 2;
        *(float4*)&Ws[row * 256 + c4] = *(const float4*)&W[(size_t)row * 1024 + colbase + c4];
    }
    int brow = blockIdx.x * 32;
    if (tid < 128)
        ((float4*)As)[tid] = ((const float4*)(A + (size_t)brow * 16))[tid];
    __syncthreads();

    int r = tid >> 3, lane8 = tid & 7;
    float a[16];
#pragma unroll
    for (int kk = 0; kk < 16; kk++) a[kk] = As[r * 16 + kk];
    __half* Cr = C + (size_t)(brow + r) * 1024 + colbase;

#pragma unroll
    for (int j = 0; j < 8; j++) {
        int col = lane8 * 4 + j * 32;
        float4 o = make_float4(bias[colbase + col],     bias[colbase + col + 1],
                               bias[colbase + col + 2], bias[colbase + col + 3]);
#pragma unroll
        for (int kk = 0; kk < 16; kk++) {
            float4 wv = *(float4*)&Ws[kk * 256 + col];
            o.x += a[kk] * wv.x; o.y += a[kk] * wv.y;
            o.z += a[kk] * wv.z; o.w += a[kk] * wv.w;
        }
        o.x = o.x / (1.f + expf(-o.x));
        o.y = o.y / (1.f + expf(-o.y));
        o.z = o.z / (1.f + expf(-o.z));
        o.w = o.w / (1.f + expf(-o.w));
        *(__half2*)&Cr[col]     = __floats2half2_rn(o.x, o.y);
        *(__half2*)&Cr[col + 2] = __floats2half2_rn(o.z, o.w);
    }
}

// ============ fp16 GEMM 128x128x64, 2-stage, 3 CTAs/SM target =======================
#define EPI_NONE 0
#define EPI_SILU 1
#define EPI_GELU 2
#define EPI_RES  3
#define EPI_MOD  4

#define GBK 64
#define GSTR 72
#define BSTR 136
#define APS  (128 * GSTR)
#define BPS  (64 * BSTR)
#define HMMA_SMEM (2 * (APS + BPS) * 2)     // 71680 B -> 3 CTAs/SM

__device__ __forceinline__ void cp16h(__half* s, const __half* g)
{
    uint32_t sa = (uint32_t)__cvta_generic_to_shared(s);
    asm volatile("cp.async.cg.shared.global [%0], [%1], 16;\n" :: "r"(sa), "l"(g));
}

__device__ __forceinline__ void mma_f16(float* c, const uint32_t* a, const uint32_t* b)
{
    asm volatile(
        "mma.sync.aligned.m16n8k16.row.col.f32.f16.f16.f32 "
        "{%0,%1,%2,%3},{%4,%5,%6,%7},{%8,%9},{%0,%1,%2,%3};"
        : "+f"(c[0]), "+f"(c[1]), "+f"(c[2]), "+f"(c[3])
        : "r"(a[0]), "r"(a[1]), "r"(a[2]), "r"(a[3]), "r"(b[0]), "r"(b[1]));
}

__device__ __forceinline__ void ldm_x4(uint32_t* r, const __half* p)
{
    uint32_t addr = (uint32_t)__cvta_generic_to_shared(p);
    asm volatile("ldmatrix.sync.aligned.m8n8.x4.shared.b16 {%0,%1,%2,%3}, [%4];"
                 : "=r"(r[0]), "=r"(r[1]), "=r"(r[2]), "=r"(r[3]) : "r"(addr));
}

__device__ __forceinline__ void ldm_x2t(uint32_t* r, const __half* p)
{
    uint32_t addr = (uint32_t)__cvta_generic_to_shared(p);
    asm volatile("ldmatrix.sync.aligned.m8n8.x2.trans.shared.b16 {%0,%1}, [%2];"
                 : "=r"(r[0]), "=r"(r[1]) : "r"(addr));
}

__device__ __forceinline__ void ldm_x4t(uint32_t* r, const __half* p)
{
    uint32_t addr = (uint32_t)__cvta_generic_to_shared(p);
    asm volatile("ldmatrix.sync.aligned.m8n8.x4.trans.shared.b16 {%0,%1,%2,%3}, [%4];"
                 : "=r"(r[0]), "=r"(r[1]), "=r"(r[2]), "=r"(r[3]) : "r"(addr));
}

template<int EPI, int HOUT>
__global__ void __launch_bounds__(256, 3) hmma_kernel(
    const __half* __restrict__ A, const __half* __restrict__ Wn,
    const float* __restrict__ bias, const float* __restrict__ Res,
    void* __restrict__ Cv, int M, int N, int K)
{
    extern __shared__ __half hsm[];
    __half* Asm = hsm;
    __half* Bsm = hsm + 2 * APS;

    int tid  = threadIdx.x;
    int brow = blockIdx.y * 128;
    int bcol = blockIdx.x * 128;
    int warp = tid >> 5, lane = tid & 31;
    int g = lane >> 2, t = lane & 3;
    int wr = warp & 1, wc = warp >> 1;

    int ar = tid >> 3, ac = (tid & 7) << 3;
    const __half* Agb = A + (size_t)(brow + ar) * K + ac;
    int br = tid >> 4, bc = (tid & 15) << 3;
    const __half* Bgb = Wn + (size_t)br * N + bcol + bc;

    int a_row  = wr * 64 + (lane & 15);
    int a_koff = (lane >> 4) << 3;
    int b_klane = lane & 15;

    float acc[4][4][4];
#pragma unroll
    for (int i = 0; i < 4; i++)
#pragma unroll
        for (int j = 0; j < 4; j++)
#pragma unroll
            for (int c = 0; c < 4; c++) acc[i][j][c] = 0.f;

    int nk = K / GBK;

    // prologue: chunks 0 and 1 into stages 0,1
#pragma unroll
    for (int s = 0; s < 2; s++) {
        int kc = s * GBK;
#pragma unroll
        for (int p = 0; p < 4; p++)
            cp16h(&Asm[s * APS + (ar + 32 * p) * GSTR + ac], Agb + (size_t)32 * p * K + kc);
#pragma unroll
        for (int p = 0; p < 4; p++)
            cp16h(&Bsm[s * BPS + (br + 16 * p) * BSTR + bc], Bgb + (size_t)(kc + 16 * p) * N);
        asm volatile("cp.async.commit_group;");
    }

    for (int i = 0; i < nk; i++) {
        int cur = i & 1;
        if (i + 1 < nk) asm volatile("cp.async.wait_group 1;" ::: "memory");
        else            asm volatile("cp.async.wait_group 0;" ::: "memory");
        __syncthreads();

        const __half* Sb = &Asm[cur * APS];
        const __half* Tb = &Bsm[cur * BPS];
#pragma unroll
        for (int ks = 0; ks < 4; ks++) {
            int k0 = ks * 16;
            uint32_t af[4][4];
#pragma unroll
            for (int ti = 0; ti < 4; ti++)
                ldm_x4(af[ti], Sb + (a_row + ti * 16) * GSTR + k0 + a_koff);
#pragma unroll
            for (int tj = 0; tj < 4; tj++) {
                uint32_t vb[2];
                ldm_x2t(vb, Tb + (size_t)(k0 + b_klane) * BSTR + wc * 32 + tj * 8);
#pragma unroll
                for (int ti = 0; ti < 4; ti++)
                    mma_f16(acc[ti][tj], af[ti], vb);
            }
        }
        __syncthreads();   // all warps done reading stage cur before overwrite

        if (i + 2 < nk) {
            int kc = (i + 2) * GBK;
#pragma unroll
            for (int p = 0; p < 4; p++)
                cp16h(&Asm[cur * APS + (ar + 32 * p) * GSTR + ac], Agb + (size_t)32 * p * K + kc);
#pragma unroll
            for (int p = 0; p < 4; p++)
                cp16h(&Bsm[cur * BPS + (br + 16 * p) * BSTR + bc], Bgb + (size_t)(kc + 16 * p) * N);
            asm volatile("cp.async.commit_group;");
        }
    }

#pragma unroll
    for (int ti = 0; ti < 4; ti++) {
        int r0 = brow + wr * 64 + ti * 16 + g;
#pragma unroll
        for (int tj = 0; tj < 4; tj++) {
            int c0 = bcol + wc * 32 + tj * 8 + 2 * t;
#pragma unroll
            for (int half_i = 0; half_i < 2; half_i++) {
                int row = r0 + half_i * 8;
                float vx = acc[ti][tj][half_i * 2 + 0];
                float vy = acc[ti][tj][half_i * 2 + 1];
                if (EPI == EPI_MOD) {
                    int j = c0 >> 1;
                    float shift = vx + bias[j];
                    float scale = vy + bias[1024 + j];
                    float res = Res[(size_t)row * (N >> 1) + j];
                    ((float*)Cv)[(size_t)row * (N >> 1) + j] = res * (1.f + scale) + shift;
                    continue;
                }
                vx += bias[c0]; vy += bias[c0 + 1];
                if (EPI == EPI_SILU) {
                    vx = vx / (1.f + expf(-vx));
                    vy = vy / (1.f + expf(-vy));
                } else if (EPI == EPI_GELU) {
                    const float cst = 0.70710678118654752f;
                    vx = 0.5f * vx * (1.f + erff(vx * cst));
                    vy = 0.5f * vy * (1.f + erff(vy * cst));
                } else if (EPI == EPI_RES) {
                    float2 rv = *(const float2*)&Res[(size_t)row * N + c0];
                    vx += rv.x; vy += rv.y;
                }
                if (HOUT) {
                    *(__half2*)((__half*)Cv + (size_t)row * N + c0) = __floats2half2_rn(vx, vy);
                } else {
                    *(float2*)((float*)Cv + (size_t)row * N + c0) = make_float2(vx, vy);
                }
            }
        }
    }
}

// ---------------- fp16 flash attention, 128x64 tiles (unchanged) --------------------
#define AST 72
#define ATT_SMEM ((128 * AST + 4 * 64 * AST) * 2)

__global__ void __launch_bounds__(256) attn_mma_kernel(
    const __half* __restrict__ QKV, __half* __restrict__ O)
{
    extern __shared__ __half asm_[];
    __half* Qs = asm_;
    __half* Ks = Qs + 128 * AST;
    __half* Vs = Ks + 2 * 64 * AST;
    __half* Ps = Qs;

    int tid = threadIdx.x, warp = tid >> 5, lane = tid & 31;
    int g = lane >> 2, t = lane & 3;
    int qt = (TT / 128 - 1) - blockIdx.x;
    int bh = blockIdx.y, b = bh >> 4, h = bh & 15;

    const __half* Qg = QKV + (size_t)b * TT * QSTR + (size_t)h * HD;
    const __half* Kg = Qg + 1024;
    const __half* Vg = Qg + 2048;

    {
        int lrow = tid >> 1, ld32 = (tid & 1) << 5;
        const __half* src = Qg + (size_t)(qt * 128 + lrow) * QSTR + ld32;
        __half* dst = Qs + lrow * AST + ld32;
        *(uint4*)(dst)      = *(const uint4*)(src);
        *(uint4*)(dst + 8)  = *(const uint4*)(src + 8);
        *(uint4*)(dst + 16) = *(const uint4*)(src + 16);
        *(uint4*)(dst + 24) = *(const uint4*)(src + 24);
    }
    int lrow = tid >> 2, ld16 = (tid & 3) << 4;
    {
        const __half* kp = Kg + (size_t)lrow * QSTR + ld16;
        const __half* vp = Vg + (size_t)lrow * QSTR + ld16;
        cp16h(&Ks[lrow * AST + ld16],     kp);
        cp16h(&Ks[lrow * AST + ld16 + 8], kp + 8);
        cp16h(&Vs[lrow * AST + ld16],     vp);
        cp16h(&Vs[lrow * AST + ld16 + 8], vp + 8);
        asm volatile("cp.async.commit_group;");
    }
    __syncthreads();

    int r0 = warp * 16 + g;
    uint32_t qf[4][4];
#pragma unroll
    for (int ks = 0; ks < 4; ks++) {
        int k0 = ks * 16;
        qf[ks][0] = *(const uint32_t*)&Qs[(r0)     * AST + k0 + 2 * t];
        qf[ks][1] = *(const uint32_t*)&Qs[(r0 + 8) * AST + k0 + 2 * t];
        qf[ks][2] = *(const uint32_t*)&Qs[(r0)     * AST + k0 + 2 * t + 8];
        qf[ks][3] = *(const uint32_t*)&Qs[(r0 + 8) * AST + k0 + 2 * t + 8];
    }
    __half* Pw = Ps + warp * 16 * AST;

    int kb_row  = ((lane >> 4) << 3) + (lane & 7);
    int kb_koff = ((lane >> 3) & 1) << 3;
    int vb_row  = lane;

    float m0 = -1e30f, m1 = -1e30f, l0 = 0.f, l1 = 0.f;
    float acc[8][4];
#pragma unroll
    for (int tj = 0; tj < 8; tj++)
#pragma unroll
        for (int c = 0; c < 4; c++) acc[tj][c] = 0.f;

    int nkt = 2 * qt + 2;
    for (int kt = 0; kt < nkt; kt++) {
        int cur = kt & 1;
        asm volatile("cp.async.wait_group 0;" ::: "memory");
        __syncthreads();

        if (kt + 1 < nkt) {
            int nxt = cur ^ 1;
            const __half* kp = Kg + (size_t)((kt + 1) * 64 + lrow) * QSTR + ld16;
            const __half* vp = Vg + (size_t)((kt + 1) * 64 + lrow) * QSTR + ld16;
            cp16h(&Ks[nxt * 64 * AST + lrow * AST + ld16],     kp);
            cp16h(&Ks[nxt * 64 * AST + lrow * AST + ld16 + 8], kp + 8);
            cp16h(&Vs[nxt * 64 * AST + lrow * AST + ld16],     vp);
            cp16h(&Vs[nxt * 64 * AST + lrow * AST + ld16 + 8], vp + 8);
        }
        asm volatile("cp.async.commit_group;");

        const __half* Kc = Ks + cur * 64 * AST;
        const __half* Vc = Vs + cur * 64 * AST;

        float s[8][4];
#pragma unroll
        for (int tj = 0; tj < 8; tj++)
#pragma unroll
            for (int c = 0; c < 4; c++) s[tj][c] = 0.f;
#pragma unroll
        for (int ks = 0; ks < 4; ks++) {
            int k0 = ks * 16;
#pragma unroll
            for (int tp = 0; tp < 4; tp++) {
                uint32_t bf4[4];
                ldm_x4(bf4, Kc + (tp * 16 + kb_row) * AST + k0 + kb_koff);
                mma_f16(s[2 * tp],     qf[ks], bf4);
                mma_f16(s[2 * tp + 1], qf[ks], bf4 + 2);
            }
        }

        if (kt >= 2 * qt) {
            int cgb = kt * 64;
            int rg0 = qt * 128 + r0, rg1 = rg0 + 8;
#pragma unroll
            for (int tj = 0; tj < 8; tj++) {
                int c0 = cgb + tj * 8 + 2 * t;
                if (c0     > rg0) s[tj][0] = -1e30f;
                if (c0 + 1 > rg0) s[tj][1] = -1e30f;
                if (c0     > rg1) s[tj][2] = -1e30f;
                if (c0 + 1 > rg1) s[tj][3] = -1e30f;
            }
        }

        float rm0 = -1e30f, rm1 = -1e30f;
#pragma unroll
        for (int tj = 0; tj < 8; tj++) {
            rm0 = fmaxf(rm0, fmaxf(s[tj][0], s[tj][1]));
            rm1 = fmaxf(rm1, fmaxf(s[tj][2], s[tj][3]));
        }
#pragma unroll
        for (int o = 1; o < 4; o <<= 1) {
            rm0 = fmaxf(rm0, __shfl_xor_sync(0xffffffffu, rm0, o));
            rm1 = fmaxf(rm1, __shfl_xor_sync(0xffffffffu, rm1, o));
        }
        float nm0 = fmaxf(m0, rm0), nm1 = fmaxf(m1, rm1);
        float a0 = __expf(m0 - nm0), a1 = __expf(m1 - nm1);
        m0 = nm0; m1 = nm1;

        float ls0 = 0.f, ls1 = 0.f;
#pragma unroll
        for (int tj = 0; tj < 8; tj++) {
            s[tj][0] = __expf(s[tj][0] - nm0);
            s[tj][1] = __expf(s[tj][1] - nm0);
            s[tj][2] = __expf(s[tj][2] - nm1);
            s[tj][3] = __expf(s[tj][3] - nm1);
            ls0 += s[tj][0] + s[tj][1];
            ls1 += s[tj][2] + s[tj][3];
        }
#pragma unroll
        for (int o = 1; o < 4; o <<= 1) {
            ls0 += __shfl_xor_sync(0xffffffffu, ls0, o);
            ls1 += __shfl_xor_sync(0xffffffffu, ls1, o);
        }
        l0 = l0 * a0 + ls0;
        l1 = l1 * a1 + ls1;

#pragma unroll
        for (int tj = 0; tj < 8; tj++) {
            int c0 = tj * 8 + 2 * t;
            *(__half2*)&Pw[(g)     * AST + c0] = __floats2half2_rn(s[tj][0], s[tj][1]);
            *(__half2*)&Pw[(g + 8) * AST + c0] = __floats2half2_rn(s[tj][2], s[tj][3]);
        }
        __syncwarp();

#pragma unroll
        for (int tj = 0; tj < 8; tj++) {
            acc[tj][0] *= a0; acc[tj][1] *= a0;
            acc[tj][2] *= a1; acc[tj][3] *= a1;
        }

#pragma unroll
        for (int kp2 = 0; kp2 < 2; kp2++) {
            int k0 = kp2 * 32;
            uint32_t pf0[4], pf1[4];
            pf0[0] = *(const uint32_t*)&Pw[(g)     * AST + k0 + 2 * t];
            pf0[1] = *(const uint32_t*)&Pw[(g + 8) * AST + k0 + 2 * t];
            pf0[2] = *(const uint32_t*)&Pw[(g)     * AST + k0 + 2 * t + 8];
            pf0[3] = *(const uint32_t*)&Pw[(g + 8) * AST + k0 + 2 * t + 8];
            pf1[0] = *(const uint32_t*)&Pw[(g)     * AST + k0 + 16 + 2 * t];
            pf1[1] = *(const uint32_t*)&Pw[(g + 8) * AST + k0 + 16 + 2 * t];
            pf1[2] = *(const uint32_t*)&Pw[(g)     * AST + k0 + 16 + 2 * t + 8];
            pf1[3] = *(const uint32_t*)&Pw[(g + 8) * AST + k0 + 16 + 2 * t + 8];
#pragma unroll
            for (int tj = 0; tj < 8; tj++) {
                uint32_t vb[4];
                ldm_x4t(vb, Vc + (k0 + vb_row) * AST + tj * 8);
                mma_f16(acc[tj], pf0, vb);
                mma_f16(acc[tj], pf1, vb + 2);
            }
        }
    }

    float inv0 = 1.f / l0, inv1 = 1.f / l1;
    __half* Og = O + (size_t)b * TT * DIMD + (size_t)(qt * 128) * DIMD + (size_t)h * HD;
#pragma unroll
    for (int tj = 0; tj < 8; tj++) {
        int c0 = tj * 8 + 2 * t;
        *(__half2*)&Og[(size_t)(r0)     * DIMD + c0] = __floats2half2_rn(acc[tj][0] * inv0, acc[tj][1] * inv0);
        *(__half2*)&Og[(size_t)(r0 + 8) * DIMD + c0] = __floats2half2_rn(acc[tj][2] * inv1, acc[tj][3] * inv1);
    }
}

// ------------------------------- launch --------------------------------------------
extern "C" void kernel_launch(void* const* d_in, const int* in_sizes, int n_in,
                              void* d_out, int out_size)
{
    const float* x       = (const float*)d_in[0];
    const float* actions = (const float*)d_in[1];
    const float* n1_w    = (const float*)d_in[2];
    const float* n2_w    = (const float*)d_in[3];
    const float* q_w     = (const float*)d_in[4];
    const float* q_b     = (const float*)d_in[5];
    const float* k_w     = (const float*)d_in[6];
    const float* k_b     = (const float*)d_in[7];
    const float* v_w     = (const float*)d_in[8];
    const float* v_b     = (const float*)d_in[9];
    const float* qn_w    = (const float*)d_in[10];
    const float* kn_w    = (const float*)d_in[11];
    const float* o_w     = (const float*)d_in[12];
    const float* o_b     = (const float*)d_in[13];
    const float* ae1_w   = (const float*)d_in[14];
    const float* ae1_b   = (const float*)d_in[15];
    const float* ae2_w   = (const float*)d_in[16];
    const float* ae2_b   = (const float*)d_in[17];
    const float* mod_w   = (const float*)d_in[18];
    const float* mod_b   = (const float*)d_in[19];
    const float* m1_w    = (const float*)d_in[20];
    const float* m1_b    = (const float*)d_in[21];
    const float* m2_w    = (const float*)d_in[22];
    const float* m2_b    = (const float*)d_in[23];
    float* out           = (float*)d_out;

    __half *h, *a1, *qkv, *ao, *ae, *hid;
    float *x1, *bqkv;
    __half *wqkv, *wo, *wae2, *wmod, *wm1, *wm2;
    cudaGetSymbolAddress((void**)&h,    g_h);
    cudaGetSymbolAddress((void**)&a1,   g_a1);
    cudaGetSymbolAddress((void**)&qkv,  g_qkv);
    cudaGetSymbolAddress((void**)&ao,   g_ao);
    cudaGetSymbolAddress((void**)&ae,   g_ae);
    cudaGetSymbolAddress((void**)&hid,  g_hid);
    cudaGetSymbolAddress((void**)&x1,   g_x1);
    cudaGetSymbolAddress((void**)&bqkv, g_bqkv);
    cudaGetSymbolAddress((void**)&wqkv, g_wqkv);
    cudaGetSymbolAddress((void**)&wo,   g_wo);
    cudaGetSymbolAddress((void**)&wae2, g_wae2);
    cudaGetSymbolAddress((void**)&wmod, g_wmod);
    cudaGetSymbolAddress((void**)&wm1,  g_wm1);
    cudaGetSymbolAddress((void**)&wm2,  g_wm2);

    static int init_done = 0;
    static cudaStream_t s1, s2;
    static cudaEvent_t evRoot, evConv, evH, evAe;
    if (!init_done) {
        cudaFuncSetAttribute((const void*)hmma_kernel<EPI_NONE, 1>, cudaFuncAttributeMaxDynamicSharedMemorySize, HMMA_SMEM);
        cudaFuncSetAttribute((const void*)hmma_kernel<EPI_SILU, 1>, cudaFuncAttributeMaxDynamicSharedMemorySize, HMMA_SMEM);
        cudaFuncSetAttribute((const void*)hmma_kernel<EPI_GELU, 1>, cudaFuncAttributeMaxDynamicSharedMemorySize, HMMA_SMEM);
        cudaFuncSetAttribute((const void*)hmma_kernel<EPI_RES,  0>, cudaFuncAttributeMaxDynamicSharedMemorySize, HMMA_SMEM);
        cudaFuncSetAttribute((const void*)hmma_kernel<EPI_MOD,  0>, cudaFuncAttributeMaxDynamicSharedMemorySize, HMMA_SMEM);
        cudaFuncSetAttribute((const void*)attn_mma_kernel, cudaFuncAttributeMaxDynamicSharedMemorySize, ATT_SMEM);
        cudaStreamCreateWithFlags(&s1, cudaStreamNonBlocking);
        cudaStreamCreateWithFlags(&s2, cudaStreamNonBlocking);
        cudaEventCreateWithFlags(&evRoot, cudaEventDisableTiming);
        cudaEventCreateWithFlags(&evConv, cudaEventDisableTiming);
        cudaEventCreateWithFlags(&evH,    cudaEventDisableTiming);
        cudaEventCreateWithFlags(&evAe,   cudaEventDisableTiming);
        init_done = 1;
    }

    dim3 g1024(8, 32);
    dim3 g2048(16, 32);
    dim3 g3072(24, 32);
    dim3 g4096(32, 32);

    // ---- fork ----
    cudaEventRecord(evRoot, 0);
    cudaStreamWaitEvent(s1, evRoot, 0);
    cudaStreamWaitEvent(s2, evRoot, 0);

    ae1_kernel<<<dim3(BT / 32, 4), 256, 0, s1>>>(actions, ae1_w, ae1_b, a1);
    rmsnorm_kernel<<<BT, 256, 0, s2>>>(x, n1_w, h);
    cudaEventRecord(evH, s2);
    conv_all_kernel<<<U_TOT / 256, 256>>>(q_w, k_w, v_w, o_w, ae2_w, mod_w, m1_w, m2_w,
                                          q_b, k_b, v_b);
    cudaEventRecord(evConv, 0);

    cudaStreamWaitEvent(s1, evConv, 0);
    hmma_kernel<EPI_SILU, 1><<<g1024, 256, HMMA_SMEM, s1>>>(a1, wae2, ae2_b, nullptr, ae, BT, DIMD, DIMD);
    cudaEventRecord(evAe, s1);

    cudaStreamWaitEvent(0, evH, 0);
    hmma_kernel<EPI_NONE, 1><<<g3072, 256, HMMA_SMEM>>>(h, wqkv, bqkv, nullptr, qkv, BT, QSTR, DIMD);
    headnorm_kernel<<<dim3((BT * NH) / 8, 2), 256>>>(qkv, qn_w, kn_w);
    attn_mma_kernel<<<dim3(TT / 128, 2 * NH), 256, ATT_SMEM>>>(qkv, ao);
    hmma_kernel<EPI_RES, 0><<<g1024, 256, HMMA_SMEM>>>(ao, wo, o_b, x, x1, BT, DIMD, DIMD);

    cudaStreamWaitEvent(0, evAe, 0);
    hmma_kernel<EPI_MOD, 0><<<g2048, 256, HMMA_SMEM>>>(ae, wmod, mod_b, x1, x1, BT, 2048, DIMD);
    rmsnorm_kernel<<<BT, 256>>>(x1, n2_w, h);
    hmma_kernel<EPI_GELU, 1><<<g4096, 256, HMMA_SMEM>>>(h, wm1, m1_b, nullptr, hid, BT, MLPH, DIMD);
    hmma_kernel<EPI_RES, 0><<<g1024, 256, HMMA_SMEM>>>(hid, wm2, m2_b, x1, out, BT, DIMD, MLPH);
}

// round 16
// speedup vs baseline: 1.3457x; 1.3457x over previous
#include <cuda_runtime.h>
#include <cuda_fp16.h>
#include <math.h>
#include <stdint.h>

#define BT    4096
#define DIMD  1024
#define NH    16
#define HD    64
#define TT    2048
#define MLPH  4096
#define QSTR  3072

// ---------------- scratch -------------------------------------------------------
__device__ __half g_h  [BT * DIMD];
__device__ __half g_a1 [BT * DIMD];
__device__ __half g_qkv[BT * QSTR];
__device__ __half g_ao [BT * DIMD];
__device__ __half g_ae [BT * DIMD];
__device__ __half g_hid[BT * MLPH];
__device__ float  g_x1 [BT * DIMD];
__device__ float  g_mod[BT * 2048];
__device__ float  g_bqkv[QSTR];
// NATURAL layout ([K][N]) fp16 weights
__device__ __half g_wqkv[DIMD * QSTR];
__device__ __half g_wo  [DIMD * DIMD];
__device__ __half g_wae2[DIMD * DIMD];
__device__ __half g_wmod[DIMD * 2048];
__device__ __half g_wm1 [DIMD * MLPH];
__device__ __half g_wm2 [MLPH * DIMD];

// ---------------- fused weight convert ----------------------------------------------
#define U_QKV  786432
#define U_O    1048576
#define U_AE2  1310720
#define U_M1   2359296
#define U_M2   3407872
#define U_MOD  3670016
#define U_TOT  3670784

__global__ void conv_all_kernel(const float* __restrict__ q_w, const float* __restrict__ k_w,
                                const float* __restrict__ v_w, const float* __restrict__ o_w,
                                const float* __restrict__ ae2_w, const float* __restrict__ mod_w,
                                const float* __restrict__ m1_w, const float* __restrict__ m2_w,
                                const float* __restrict__ q_b, const float* __restrict__ k_b,
                                const float* __restrict__ v_b)
{
    int u = blockIdx.x * 256 + threadIdx.x;
    if (u < U_QKV) {
        int j = u >> 18, r = u & 262143;
        int k = r >> 8, n4 = (r & 255) << 2;
        const float* s = (j == 0) ? q_w : ((j == 1) ? k_w : v_w);
        float4 v = *(const float4*)&s[(size_t)k * 1024 + n4];
        uint2 o;
        ((__half2*)&o)[0] = __floats2half2_rn(v.x, v.y);
        ((__half2*)&o)[1] = __floats2half2_rn(v.z, v.w);
        *(uint2*)&g_wqkv[(size_t)k * QSTR + j * 1024 + n4] = o;
    } else if (u < U_O) {
        int e4 = (u - U_QKV) << 2;
        float4 v = *(const float4*)&o_w[e4];
        uint2 o;
        ((__half2*)&o)[0] = __floats2half2_rn(v.x, v.y);
        ((__half2*)&o)[1] = __floats2half2_rn(v.z, v.w);
        *(uint2*)&g_wo[e4] = o;
    } else if (u < U_AE2) {
        int e4 = (u - U_O) << 2;
        float4 v = *(const float4*)&ae2_w[e4];
        uint2 o;
        ((__half2*)&o)[0] = __floats2half2_rn(v.x, v.y);
        ((__half2*)&o)[1] = __floats2half2_rn(v.z, v.w);
        *(uint2*)&g_wae2[e4] = o;
    } else if (u < U_M1) {
        int e4 = (u - U_AE2) << 2;
        float4 v = *(const float4*)&m1_w[e4];
        uint2 o;
        ((__half2*)&o)[0] = __floats2half2_rn(v.x, v.y);
        ((__half2*)&o)[1] = __floats2half2_rn(v.z, v.w);
        *(uint2*)&g_wm1[e4] = o;
    } else if (u < U_M2) {
        int e4 = (u - U_M1) << 2;
        float4 v = *(const float4*)&m2_w[e4];
        uint2 o;
        ((__half2*)&o)[0] = __floats2half2_rn(v.x, v.y);
        ((__half2*)&o)[1] = __floats2half2_rn(v.z, v.w);
        *(uint2*)&g_wm2[e4] = o;
    } else if (u < U_MOD) {
        int r = u - U_M2;
        int k = r >> 8, j4 = (r & 255) << 2;
        float4 sh = *(const float4*)&mod_w[(size_t)k * 4096 + j4];
        float4 sc = *(const float4*)&mod_w[(size_t)k * 4096 + 1024 + j4];
        uint4 o;
        ((__half2*)&o)[0] = __floats2half2_rn(sh.x, sc.x);
        ((__half2*)&o)[1] = __floats2half2_rn(sh.y, sc.y);
        ((__half2*)&o)[2] = __floats2half2_rn(sh.z, sc.z);
        ((__half2*)&o)[3] = __floats2half2_rn(sh.w, sc.w);
        *(uint4*)&g_wmod[(size_t)k * 2048 + 2 * j4] = o;
    } else {
        int r = u - U_MOD;
        int i = r << 2;
        float4 v;
        if (i < 1024)      v = *(const float4*)&q_b[i];
        else if (i < 2048) v = *(const float4*)&k_b[i - 1024];
        else               v = *(const float4*)&v_b[i - 2048];
        *(float4*)&g_bqkv[i] = v;
    }
}

// ---------------- rmsnorm ------------------------------------------------------------
__global__ void rmsnorm_kernel(const float* __restrict__ x,
                               const float* __restrict__ w,
                               __half* __restrict__ y)
{
    int row = blockIdx.x;
    const float* xr = x + (size_t)row * DIMD;
    float v[4];
    float s = 0.f;
#pragma unroll
    for (int i = 0; i < 4; i++) {
        v[i] = xr[threadIdx.x + i * 256];
        s += v[i] * v[i];
    }
#pragma unroll
    for (int o = 16; o > 0; o >>= 1) s += __shfl_xor_sync(0xffffffffu, s, o);
    __shared__ float red[8];
    if ((threadIdx.x & 31) == 0) red[threadIdx.x >> 5] = s;
    __syncthreads();
    if (threadIdx.x == 0) {
        float t = 0.f;
#pragma unroll
        for (int i = 0; i < 8; i++) t += red[i];
        red[0] = rsqrtf(t * (1.0f / DIMD) + 1e-6f);
    }
    __syncthreads();
    float r = red[0];
    __half* yr = y + (size_t)row * DIMD;
#pragma unroll
    for (int i = 0; i < 4; i++) {
        int c = threadIdx.x + i * 256;
        yr[c] = __float2half_rn(v[i] * r * w[c]);
    }
}

// ---------------- modulate: x1 = x1*(1+scale)+shift from interleaved mod -------------
__global__ void modulate_kernel(float* __restrict__ x, const float* __restrict__ mod)
{
    int idx = blockIdx.x * 256 + threadIdx.x;
    int row = idx >> 10;
    int col = idx & 1023;
    float2 ss = *(const float2*)&mod[(size_t)row * 2048 + 2 * col];
    x[idx] = x[idx] * (1.0f + ss.y) + ss.x;
}

// ---------------- per-head rmsnorm on qkv buffer --------------------------------------
__global__ void headnorm_kernel(__half* __restrict__ qkv,
                                const float* __restrict__ qw, const float* __restrict__ kw)
{
    int sel = blockIdx.y;
    const float* w = sel ? kw : qw;
    float scale = sel ? 1.0f : 0.125f;
    int gw   = (blockIdx.x * blockDim.x + threadIdx.x) >> 5;
    int lane = threadIdx.x & 31;
    if (gw >= BT * NH) return;
    int token = gw >> 4, head = gw & 15;
    __half* p = qkv + (size_t)token * QSTR + sel * 1024 + head * 64;
    float a = __half2float(p[lane]);
    float b = __half2float(p[lane + 32]);
    float s = a * a + b * b;
#pragma unroll
    for (int o = 16; o > 0; o >>= 1) s += __shfl_xor_sync(0xffffffffu, s, o);
    float r = rsqrtf(s * (1.0f / HD) + 1e-6f) * scale;
    p[lane]      = __float2half_rn(a * r * w[lane]);
    p[lane + 32] = __float2half_rn(b * r * w[lane + 32]);
}

// ---------------- ae1 (K=16) -----------------------------------------------------------
__global__ void __launch_bounds__(256) ae1_kernel(
    const float* __restrict__ A, const float* __restrict__ W,
    const float* __restrict__ bias, __half* __restrict__ C)
{
    __shared__ float Ws[16 * 256];
    __shared__ float As[32 * 16];
    int tid = threadIdx.x;
    int colbase = blockIdx.y * 256;
    for (int i = tid; i < 1024; i += 256) {
        int row = i >> 6, c4 = (i & 63) << 2;
        *(float4*)&Ws[row * 256 + c4] = *(const float4*)&W[(size_t)row * 1024 + colbase + c4];
    }
    int brow = blockIdx.x * 32;
    if (tid < 128)
        ((float4*)As)[tid] = ((const float4*)(A + (size_t)brow * 16))[tid];
    __syncthreads();

    int r = tid >> 3, lane8 = tid & 7;
    float a[16];
#pragma unroll
    for (int kk = 0; kk < 16; kk++) a[kk] = As[r * 16 + kk];
    __half* Cr = C + (size_t)(brow + r) * 1024 + colbase;

#pragma unroll
    for (int j = 0; j < 8; j++) {
        int col = lane8 * 4 + j * 32;
        float4 o = make_float4(bias[colbase + col],     bias[colbase + col + 1],
                               bias[colbase + col + 2], bias[colbase + col + 3]);
#pragma unroll
        for (int kk = 0; kk < 16; kk++) {
            float4 wv = *(float4*)&Ws[kk * 256 + col];
            o.x += a[kk] * wv.x; o.y += a[kk] * wv.y;
            o.z += a[kk] * wv.z; o.w += a[kk] * wv.w;
        }
        o.x = o.x / (1.f + expf(-o.x));
        o.y = o.y / (1.f + expf(-o.y));
        o.z = o.z / (1.f + expf(-o.z));
        o.w = o.w / (1.f + expf(-o.w));
        *(__half2*)&Cr[col]     = __floats2half2_rn(o.x, o.y);
        *(__half2*)&Cr[col + 2] = __floats2half2_rn(o.z, o.w);
    }
}

// ============ fp16 GEMM 128x128x64, 3-stage (round-14 known-good) ===================
#define EPI_NONE  0
#define EPI_SILU  1
#define EPI_GELU  2
#define EPI_RES   3
#define EPI_MODST 5

#define GBK 64
#define GSTR 72
#define BSTR 136
#define APS  (128 * GSTR)
#define BPS  (64 * BSTR)
#define HMMA_SMEM (3 * (APS + BPS) * 2)

__device__ __forceinline__ void cp16h(__half* s, const __half* g)
{
    uint32_t sa = (uint32_t)__cvta_generic_to_shared(s);
    asm volatile("cp.async.cg.shared.global [%0], [%1], 16;\n" :: "r"(sa), "l"(g));
}

__device__ __forceinline__ void mma_f16(float* c, const uint32_t* a, const uint32_t* b)
{
    asm volatile(
        "mma.sync.aligned.m16n8k16.row.col.f32.f16.f16.f32 "
        "{%0,%1,%2,%3},{%4,%5,%6,%7},{%8,%9},{%0,%1,%2,%3};"
        : "+f"(c[0]), "+f"(c[1]), "+f"(c[2]), "+f"(c[3])
        : "r"(a[0]), "r"(a[1]), "r"(a[2]), "r"(a[3]), "r"(b[0]), "r"(b[1]));
}

__device__ __forceinline__ void ldm_x4(uint32_t* r, const __half* p)
{
    uint32_t addr = (uint32_t)__cvta_generic_to_shared(p);
    asm volatile("ldmatrix.sync.aligned.m8n8.x4.shared.b16 {%0,%1,%2,%3}, [%4];"
                 : "=r"(r[0]), "=r"(r[1]), "=r"(r[2]), "=r"(r[3]) : "r"(addr));
}

__device__ __forceinline__ void ldm_x4t(uint32_t* r, const __half* p)
{
    uint32_t addr = (uint32_t)__cvta_generic_to_shared(p);
    asm volatile("ldmatrix.sync.aligned.m8n8.x4.trans.shared.b16 {%0,%1,%2,%3}, [%4];"
                 : "=r"(r[0]), "=r"(r[1]), "=r"(r[2]), "=r"(r[3]) : "r"(addr));
}

template<int EPI, int HOUT>
__global__ void __launch_bounds__(256, 2) hmma_kernel(
    const __half* __restrict__ A, const __half* __restrict__ Wn,
    const float* __restrict__ bias, const float* __restrict__ Res,
    void* __restrict__ Cv, int M, int N, int K)
{
    extern __shared__ __half hsm[];
    __half* Asm = hsm;
    __half* Bsm = hsm + 3 * APS;

    int tid  = threadIdx.x;
    int brow = blockIdx.y * 128;
    int bcol = blockIdx.x * 128;
    int warp = tid >> 5, lane = tid & 31;
    int g = lane >> 2, t = lane & 3;
    int wr = warp & 1, wc = warp >> 1;

    int ar = tid >> 3, ac = (tid & 7) << 3;
    const __half* Agb = A + (size_t)(brow + ar) * K + ac;
    int br = tid >> 4, bc = (tid & 15) << 3;
    const __half* Bgb = Wn + (size_t)br * N + bcol + bc;

    int a_row  = wr * 64 + (lane & 15);
    int a_koff = (lane >> 4) << 3;

    float acc[4][4][4];
#pragma unroll
    for (int i = 0; i < 4; i++)
#pragma unroll
        for (int j = 0; j < 4; j++)
#pragma unroll
            for (int c = 0; c < 4; c++) acc[i][j][c] = 0.f;

    int nk = K / GBK;

#pragma unroll
    for (int s = 0; s < 2; s++) {
        int kc = s * GBK;
#pragma unroll
        for (int p = 0; p < 4; p++)
            cp16h(&Asm[s * APS + (ar + 32 * p) * GSTR + ac], Agb + (size_t)32 * p * K + kc);
#pragma unroll
        for (int p = 0; p < 4; p++)
            cp16h(&Bsm[s * BPS + (br + 16 * p) * BSTR + bc], Bgb + (size_t)(kc + 16 * p) * N);
        asm volatile("cp.async.commit_group;");
    }

    int st = 0;
    for (int i = 0; i < nk; i++) {
        asm volatile("cp.async.wait_group 1;" ::: "memory");
        __syncthreads();

        if (i + 2 < nk) {
            int kc = (i + 2) * GBK;
            int s2 = st + 2; if (s2 >= 3) s2 -= 3;
#pragma unroll
            for (int p = 0; p < 4; p++)
                cp16h(&Asm[s2 * APS + (ar + 32 * p) * GSTR + ac], Agb + (size_t)32 * p * K + kc);
#pragma unroll
            for (int p = 0; p < 4; p++)
                cp16h(&Bsm[s2 * BPS + (br + 16 * p) * BSTR + bc], Bgb + (size_t)(kc + 16 * p) * N);
        }
        asm volatile("cp.async.commit_group;");

        const __half* Sb = &Asm[st * APS];
        const __half* Tb = &Bsm[st * BPS];
#pragma unroll
        for (int kp2 = 0; kp2 < 2; kp2++) {
            int k0 = kp2 * 32;
            uint32_t af[2][4][4];
#pragma unroll
            for (int ti = 0; ti < 4; ti++) {
                ldm_x4(af[0][ti], Sb + (a_row + ti * 16) * GSTR + k0 + a_koff);
                ldm_x4(af[1][ti], Sb + (a_row + ti * 16) * GSTR + k0 + 16 + a_koff);
            }
#pragma unroll
            for (int tj = 0; tj < 4; tj++) {
                uint32_t vb[4];
                ldm_x4t(vb, Tb + (size_t)(k0 + lane) * BSTR + wc * 32 + tj * 8);
#pragma unroll
                for (int ti = 0; ti < 4; ti++) {
                    mma_f16(acc[ti][tj], af[0][ti], vb);
                    mma_f16(acc[ti][tj], af[1][ti], vb + 2);
                }
            }
        }
        if (++st == 3) st = 0;
    }

#pragma unroll
    for (int ti = 0; ti < 4; ti++) {
        int r0 = brow + wr * 64 + ti * 16 + g;
#pragma unroll
        for (int tj = 0; tj < 4; tj++) {
            int c0 = bcol + wc * 32 + tj * 8 + 2 * t;
#pragma unroll
            for (int half_i = 0; half_i < 2; half_i++) {
                int row = r0 + half_i * 8;
                float vx = acc[ti][tj][half_i * 2 + 0];
                float vy = acc[ti][tj][half_i * 2 + 1];
                if (EPI == EPI_MODST) {
                    int j = c0 >> 1;
                    float2 o = make_float2(vx + bias[j], vy + bias[1024 + j]);
                    *(float2*)((float*)Cv + (size_t)row * N + c0) = o;
                    continue;
                }
                vx += bias[c0]; vy += bias[c0 + 1];
                if (EPI == EPI_SILU) {
                    vx = vx / (1.f + expf(-vx));
                    vy = vy / (1.f + expf(-vy));
                } else if (EPI == EPI_GELU) {
                    const float cst = 0.70710678118654752f;
                    vx = 0.5f * vx * (1.f + erff(vx * cst));
                    vy = 0.5f * vy * (1.f + erff(vy * cst));
                } else if (EPI == EPI_RES) {
                    float2 rv = *(const float2*)&Res[(size_t)row * N + c0];
                    vx += rv.x; vy += rv.y;
                }
                if (HOUT) {
                    *(__half2*)((__half*)Cv + (size_t)row * N + c0) = __floats2half2_rn(vx, vy);
                } else {
                    *(float2*)((float*)Cv + (size_t)row * N + c0) = make_float2(vx, vy);
                }
            }
        }
    }
}

// ---------------- fp16 flash attention, 128x64 tiles (unchanged) --------------------
#define AST 72
#define ATT_SMEM ((128 * AST + 4 * 64 * AST) * 2)

__global__ void __launch_bounds__(256) attn_mma_kernel(
    const __half* __restrict__ QKV, __half* __restrict__ O)
{
    extern __shared__ __half asm_[];
    __half* Qs = asm_;
    __half* Ks = Qs + 128 * AST;
    __half* Vs = Ks + 2 * 64 * AST;
    __half* Ps = Qs;

    int tid = threadIdx.x, warp = tid >> 5, lane = tid & 31;
    int g = lane >> 2, t = lane & 3;
    int qt = (TT / 128 - 1) - blockIdx.x;
    int bh = blockIdx.y, b = bh >> 4, h = bh & 15;

    const __half* Qg = QKV + (size_t)b * TT * QSTR + (size_t)h * HD;
    const __half* Kg = Qg + 1024;
    const __half* Vg = Qg + 2048;

    {
        int lrow = tid >> 1, ld32 = (tid & 1) << 5;
        const __half* src = Qg + (size_t)(qt * 128 + lrow) * QSTR + ld32;
        __half* dst = Qs + lrow * AST + ld32;
        *(uint4*)(dst)      = *(const uint4*)(src);
        *(uint4*)(dst + 8)  = *(const uint4*)(src + 8);
        *(uint4*)(dst + 16) = *(const uint4*)(src + 16);
        *(uint4*)(dst + 24) = *(const uint4*)(src + 24);
    }
    int lrow = tid >> 2, ld16 = (tid & 3) << 4;
    {
        const __half* kp = Kg + (size_t)lrow * QSTR + ld16;
        const __half* vp = Vg + (size_t)lrow * QSTR + ld16;
        cp16h(&Ks[lrow * AST + ld16],     kp);
        cp16h(&Ks[lrow * AST + ld16 + 8], kp + 8);
        cp16h(&Vs[lrow * AST + ld16],     vp);
        cp16h(&Vs[lrow * AST + ld16 + 8], vp + 8);
        asm volatile("cp.async.commit_group;");
    }
    __syncthreads();

    int r0 = warp * 16 + g;
    uint32_t qf[4][4];
#pragma unroll
    for (int ks = 0; ks < 4; ks++) {
        int k0 = ks * 16;
        qf[ks][0] = *(const uint32_t*)&Qs[(r0)     * AST + k0 + 2 * t];
        qf[ks][1] = *(const uint32_t*)&Qs[(r0 + 8) * AST + k0 + 2 * t];
        qf[ks][2] = *(const uint32_t*)&Qs[(r0)     * AST + k0 + 2 * t + 8];
        qf[ks][3] = *(const uint32_t*)&Qs[(r0 + 8) * AST + k0 + 2 * t + 8];
    }
    __half* Pw = Ps + warp * 16 * AST;

    int kb_row  = ((lane >> 4) << 3) + (lane & 7);
    int kb_koff = ((lane >> 3) & 1) << 3;
    int vb_row  = lane;

    float m0 = -1e30f, m1 = -1e30f, l0 = 0.f, l1 = 0.f;
    float acc[8][4];
#pragma unroll
    for (int tj = 0; tj < 8; tj++)
#pragma unroll
        for (int c = 0; c < 4; c++) acc[tj][c] = 0.f;

    int nkt = 2 * qt + 2;
    for (int kt = 0; kt < nkt; kt++) {
        int cur = kt & 1;
        asm volatile("cp.async.wait_group 0;" ::: "memory");
        __syncthreads();

        if (kt + 1 < nkt) {
            int nxt = cur ^ 1;
            const __half* kp = Kg + (size_t)((kt + 1) * 64 + lrow) * QSTR + ld16;
            const __half* vp = Vg + (size_t)((kt + 1) * 64 + lrow) * QSTR + ld16;
            cp16h(&Ks[nxt * 64 * AST + lrow * AST + ld16],     kp);
            cp16h(&Ks[nxt * 64 * AST + lrow * AST + ld16 + 8], kp + 8);
            cp16h(&Vs[nxt * 64 * AST + lrow * AST + ld16],     vp);
            cp16h(&Vs[nxt * 64 * AST + lrow * AST + ld16 + 8], vp + 8);
        }
        asm volatile("cp.async.commit_group;");

        const __half* Kc = Ks + cur * 64 * AST;
        const __half* Vc = Vs + cur * 64 * AST;

        float s[8][4];
#pragma unroll
        for (int tj = 0; tj < 8; tj++)
#pragma unroll
            for (int c = 0; c < 4; c++) s[tj][c] = 0.f;
#pragma unroll
        for (int ks = 0; ks < 4; ks++) {
            int k0 = ks * 16;
#pragma unroll
            for (int tp = 0; tp < 4; tp++) {
                uint32_t bf4[4];
                ldm_x4(bf4, Kc + (tp * 16 + kb_row) * AST + k0 + kb_koff);
                mma_f16(s[2 * tp],     qf[ks], bf4);
                mma_f16(s[2 * tp + 1], qf[ks], bf4 + 2);
            }
        }

        if (kt >= 2 * qt) {
            int cgb = kt * 64;
            int rg0 = qt * 128 + r0, rg1 = rg0 + 8;
#pragma unroll
            for (int tj = 0; tj < 8; tj++) {
                int c0 = cgb + tj * 8 + 2 * t;
                if (c0     > rg0) s[tj][0] = -1e30f;
                if (c0 + 1 > rg0) s[tj][1] = -1e30f;
                if (c0     > rg1) s[tj][2] = -1e30f;
                if (c0 + 1 > rg1) s[tj][3] = -1e30f;
            }
        }

        float rm0 = -1e30f, rm1 = -1e30f;
#pragma unroll
        for (int tj = 0; tj < 8; tj++) {
            rm0 = fmaxf(rm0, fmaxf(s[tj][0], s[tj][1]));
            rm1 = fmaxf(rm1, fmaxf(s[tj][2], s[tj][3]));
        }
#pragma unroll
        for (int o = 1; o < 4; o <<= 1) {
            rm0 = fmaxf(rm0, __shfl_xor_sync(0xffffffffu, rm0, o));
            rm1 = fmaxf(rm1, __shfl_xor_sync(0xffffffffu, rm1, o));
        }
        float nm0 = fmaxf(m0, rm0), nm1 = fmaxf(m1, rm1);
        float a0 = __expf(m0 - nm0), a1 = __expf(m1 - nm1);
        m0 = nm0; m1 = nm1;

        float ls0 = 0.f, ls1 = 0.f;
#pragma unroll
        for (int tj = 0; tj < 8; tj++) {
            s[tj][0] = __expf(s[tj][0] - nm0);
            s[tj][1] = __expf(s[tj][1] - nm0);
            s[tj][2] = __expf(s[tj][2] - nm1);
            s[tj][3] = __expf(s[tj][3] - nm1);
            ls0 += s[tj][0] + s[tj][1];
            ls1 += s[tj][2] + s[tj][3];
        }
#pragma unroll
        for (int o = 1; o < 4; o <<= 1) {
            ls0 += __shfl_xor_sync(0xffffffffu, ls0, o);
            ls1 += __shfl_xor_sync(0xffffffffu, ls1, o);
        }
        l0 = l0 * a0 + ls0;
        l1 = l1 * a1 + ls1;

#pragma unroll
        for (int tj = 0; tj < 8; tj++) {
            int c0 = tj * 8 + 2 * t;
            *(__half2*)&Pw[(g)     * AST + c0] = __floats2half2_rn(s[tj][0], s[tj][1]);
            *(__half2*)&Pw[(g + 8) * AST + c0] = __floats2half2_rn(s[tj][2], s[tj][3]);
        }
        __syncwarp();

#pragma unroll
        for (int tj = 0; tj < 8; tj++) {
            acc[tj][0] *= a0; acc[tj][1] *= a0;
            acc[tj][2] *= a1; acc[tj][3] *= a1;
        }

#pragma unroll
        for (int kp2 = 0; kp2 < 2; kp2++) {
            int k0 = kp2 * 32;
            uint32_t pf0[4], pf1[4];
            pf0[0] = *(const uint32_t*)&Pw[(g)     * AST + k0 + 2 * t];
            pf0[1] = *(const uint32_t*)&Pw[(g + 8) * AST + k0 + 2 * t];
            pf0[2] = *(const uint32_t*)&Pw[(g)     * AST + k0 + 2 * t + 8];
            pf0[3] = *(const uint32_t*)&Pw[(g + 8) * AST + k0 + 2 * t + 8];
            pf1[0] = *(const uint32_t*)&Pw[(g)     * AST + k0 + 16 + 2 * t];
            pf1[1] = *(const uint32_t*)&Pw[(g + 8) * AST + k0 + 16 + 2 * t];
            pf1[2] = *(const uint32_t*)&Pw[(g)     * AST + k0 + 16 + 2 * t + 8];
            pf1[3] = *(const uint32_t*)&Pw[(g + 8) * AST + k0 + 16 + 2 * t + 8];
#pragma unroll
            for (int tj = 0; tj < 8; tj++) {
                uint32_t vb[4];
                ldm_x4t(vb, Vc + (k0 + vb_row) * AST + tj * 8);
                mma_f16(acc[tj], pf0, vb);
                mma_f16(acc[tj], pf1, vb + 2);
            }
        }
    }

    float inv0 = 1.f / l0, inv1 = 1.f / l1;
    __half* Og = O + (size_t)b * TT * DIMD + (size_t)(qt * 128) * DIMD + (size_t)h * HD;
#pragma unroll
    for (int tj = 0; tj < 8; tj++) {
        int c0 = tj * 8 + 2 * t;
        *(__half2*)&Og[(size_t)(r0)     * DIMD + c0] = __floats2half2_rn(acc[tj][0] * inv0, acc[tj][1] * inv0);
        *(__half2*)&Og[(size_t)(r0 + 8) * DIMD + c0] = __floats2half2_rn(acc[tj][2] * inv1, acc[tj][3] * inv1);
    }
}

// ------------------------------- launch --------------------------------------------
extern "C" void kernel_launch(void* const* d_in, const int* in_sizes, int n_in,
                              void* d_out, int out_size)
{
    const float* x       = (const float*)d_in[0];
    const float* actions = (const float*)d_in[1];
    const float* n1_w    = (const float*)d_in[2];
    const float* n2_w    = (const float*)d_in[3];
    const float* q_w     = (const float*)d_in[4];
    const float* q_b     = (const float*)d_in[5];
    const float* k_w     = (const float*)d_in[6];
    const float* k_b     = (const float*)d_in[7];
    const float* v_w     = (const float*)d_in[8];
    const float* v_b     = (const float*)d_in[9];
    const float* qn_w    = (const float*)d_in[10];
    const float* kn_w    = (const float*)d_in[11];
    const float* o_w     = (const float*)d_in[12];
    const float* o_b     = (const float*)d_in[13];
    const float* ae1_w   = (const float*)d_in[14];
    const float* ae1_b   = (const float*)d_in[15];
    const float* ae2_w   = (const float*)d_in[16];
    const float* ae2_b   = (const float*)d_in[17];
    const float* mod_w   = (const float*)d_in[18];
    const float* mod_b   = (const float*)d_in[19];
    const float* m1_w    = (const float*)d_in[20];
    const float* m1_b    = (const float*)d_in[21];
    const float* m2_w    = (const float*)d_in[22];
    const float* m2_b    = (const float*)d_in[23];
    float* out           = (float*)d_out;

    __half *h, *a1, *qkv, *ao, *ae, *hid;
    float *x1, *mod, *bqkv;
    __half *wqkv, *wo, *wae2, *wmod, *wm1, *wm2;
    cudaGetSymbolAddress((void**)&h,    g_h);
    cudaGetSymbolAddress((void**)&a1,   g_a1);
    cudaGetSymbolAddress((void**)&qkv,  g_qkv);
    cudaGetSymbolAddress((void**)&ao,   g_ao);
    cudaGetSymbolAddress((void**)&ae,   g_ae);
    cudaGetSymbolAddress((void**)&hid,  g_hid);
    cudaGetSymbolAddress((void**)&x1,   g_x1);
    cudaGetSymbolAddress((void**)&mod,  g_mod);
    cudaGetSymbolAddress((void**)&bqkv, g_bqkv);
    cudaGetSymbolAddress((void**)&wqkv, g_wqkv);
    cudaGetSymbolAddress((void**)&wo,   g_wo);
    cudaGetSymbolAddress((void**)&wae2, g_wae2);
    cudaGetSymbolAddress((void**)&wmod, g_wmod);
    cudaGetSymbolAddress((void**)&wm1,  g_wm1);
    cudaGetSymbolAddress((void**)&wm2,  g_wm2);

    static int init_done = 0;
    static cudaStream_t s1, s2;
    static cudaEvent_t evRoot, evConv, evH, evMod;
    if (!init_done) {
        cudaFuncSetAttribute((const void*)hmma_kernel<EPI_NONE,  1>, cudaFuncAttributeMaxDynamicSharedMemorySize, HMMA_SMEM);
        cudaFuncSetAttribute((const void*)hmma_kernel<EPI_SILU,  1>, cudaFuncAttributeMaxDynamicSharedMemorySize, HMMA_SMEM);
        cudaFuncSetAttribute((const void*)hmma_kernel<EPI_GELU,  1>, cudaFuncAttributeMaxDynamicSharedMemorySize, HMMA_SMEM);
        cudaFuncSetAttribute((const void*)hmma_kernel<EPI_RES,   0>, cudaFuncAttributeMaxDynamicSharedMemorySize, HMMA_SMEM);
        cudaFuncSetAttribute((const void*)hmma_kernel<EPI_MODST, 0>, cudaFuncAttributeMaxDynamicSharedMemorySize, HMMA_SMEM);
        cudaFuncSetAttribute((const void*)attn_mma_kernel, cudaFuncAttributeMaxDynamicSharedMemorySize, ATT_SMEM);
        cudaStreamCreateWithFlags(&s1, cudaStreamNonBlocking);
        cudaStreamCreateWithFlags(&s2, cudaStreamNonBlocking);
        cudaEventCreateWithFlags(&evRoot, cudaEventDisableTiming);
        cudaEventCreateWithFlags(&evConv, cudaEventDisableTiming);
        cudaEventCreateWithFlags(&evH,    cudaEventDisableTiming);
        cudaEventCreateWithFlags(&evMod,  cudaEventDisableTiming);
        init_done = 1;
    }

    dim3 g1024(8, 32);
    dim3 g2048(16, 32);
    dim3 g3072(24, 32);
    dim3 g4096(32, 32);

    // ---- fork ----
    cudaEventRecord(evRoot, 0);
    cudaStreamWaitEvent(s1, evRoot, 0);
    cudaStreamWaitEvent(s2, evRoot, 0);

    // s1: ae branch (entirely off the critical path)
    ae1_kernel<<<dim3(BT / 32, 4), 256, 0, s1>>>(actions, ae1_w, ae1_b, a1);
    // s2: rmsnorm1
    rmsnorm_kernel<<<BT, 256, 0, s2>>>(x, n1_w, h);
    cudaEventRecord(evH, s2);
    // s0: weight convert
    conv_all_kernel<<<U_TOT / 256, 256>>>(q_w, k_w, v_w, o_w, ae2_w, mod_w, m1_w, m2_w,
                                          q_b, k_b, v_b);
    cudaEventRecord(evConv, 0);

    // s1: ae2 GEMM then mod GEMM -> g_mod (overlaps s0's qkv/attention span)
    cudaStreamWaitEvent(s1, evConv, 0);
    hmma_kernel<EPI_SILU, 1><<<g1024, 256, HMMA_SMEM, s1>>>(a1, wae2, ae2_b, nullptr, ae, BT, DIMD, DIMD);
    hmma_kernel<EPI_MODST, 0><<<g2048, 256, HMMA_SMEM, s1>>>(ae, wmod, mod_b, nullptr, mod, BT, 2048, DIMD);
    cudaEventRecord(evMod, s1);

    // s0: qkv projection, headnorm, attention, O-proj
    cudaStreamWaitEvent(0, evH, 0);
    hmma_kernel<EPI_NONE, 1><<<g3072, 256, HMMA_SMEM>>>(h, wqkv, bqkv, nullptr, qkv, BT, QSTR, DIMD);
    headnorm_kernel<<<dim3((BT * NH) / 8, 2), 256>>>(qkv, qn_w, kn_w);
    attn_mma_kernel<<<dim3(TT / 128, 2 * NH), 256, ATT_SMEM>>>(qkv, ao);
    hmma_kernel<EPI_RES, 0><<<g1024, 256, HMMA_SMEM>>>(ao, wo, o_b, x, x1, BT, DIMD, DIMD);

    // join: elementwise modulate (needs x1 and g_mod)
    cudaStreamWaitEvent(0, evMod, 0);
    modulate_kernel<<<(BT * DIMD) / 256, 256>>>(x1, mod);
    // s0: MLP
    rmsnorm_kernel<<<BT, 256>>>(x1, n2_w, h);
    hmma_kernel<EPI_GELU, 1><<<g4096, 256, HMMA_SMEM>>>(h, wm1, m1_b, nullptr, hid, BT, MLPH, DIMD);
    hmma_kernel<EPI_RES, 0><<<g1024, 256, HMMA_SMEM>>>(hid, wm2, m2_b, x1, out, BT, DIMD, MLPH);
}

// round 17
// speedup vs baseline: 1.6844x; 1.2517x over previous
#include <cuda_runtime.h>
#include <cuda_fp16.h>
#include <math.h>
#include <stdint.h>

#define BT    4096
#define DIMD  1024
#define NH    16
#define HD    64
#define TT    2048
#define MLPH  4096
#define QSTR  3072

// ---------------- scratch -------------------------------------------------------
__device__ __half g_h  [BT * DIMD];
__device__ __half g_a1 [BT * DIMD];
__device__ __half g_qkv[BT * QSTR];
__device__ __half g_ao [BT * DIMD];
__device__ __half g_ae [BT * DIMD];
__device__ __half g_hid[BT * MLPH];
__device__ float  g_x1 [BT * DIMD];
__device__ float  g_bqkv[QSTR];
// NATURAL layout ([K][N]) fp16 weights
__device__ __half g_wqkv[DIMD * QSTR];
__device__ __half g_wo  [DIMD * DIMD];
__device__ __half g_wae2[DIMD * DIMD];
__device__ __half g_wmod[DIMD * 2048];     // col 2j=shift_j, 2j+1=scale_j
__device__ __half g_wm1 [DIMD * MLPH];
__device__ __half g_wm2 [MLPH * DIMD];

// ---------------- fused weight convert ----------------------------------------------
#define U_QKV  786432
#define U_O    1048576
#define U_AE2  1310720
#define U_M1   2359296
#define U_M2   3407872
#define U_MOD  3670016
#define U_TOT  3670784

__global__ void conv_all_kernel(const float* __restrict__ q_w, const float* __restrict__ k_w,
                                const float* __restrict__ v_w, const float* __restrict__ o_w,
                                const float* __restrict__ ae2_w, const float* __restrict__ mod_w,
                                const float* __restrict__ m1_w, const float* __restrict__ m2_w,
                                const float* __restrict__ q_b, const float* __restrict__ k_b,
                                const float* __restrict__ v_b)
{
    int u = blockIdx.x * 256 + threadIdx.x;
    if (u < U_QKV) {
        int j = u >> 18, r = u & 262143;
        int k = r >> 8, n4 = (r & 255) << 2;
        const float* s = (j == 0) ? q_w : ((j == 1) ? k_w : v_w);
        float4 v = *(const float4*)&s[(size_t)k * 1024 + n4];
        uint2 o;
        ((__half2*)&o)[0] = __floats2half2_rn(v.x, v.y);
        ((__half2*)&o)[1] = __floats2half2_rn(v.z, v.w);
        *(uint2*)&g_wqkv[(size_t)k * QSTR + j * 1024 + n4] = o;
    } else if (u < U_O) {
        int e4 = (u - U_QKV) << 2;
        float4 v = *(const float4*)&o_w[e4];
        uint2 o;
        ((__half2*)&o)[0] = __floats2half2_rn(v.x, v.y);
        ((__half2*)&o)[1] = __floats2half2_rn(v.z, v.w);
        *(uint2*)&g_wo[e4] = o;
    } else if (u < U_AE2) {
        int e4 = (u - U_O) << 2;
        float4 v = *(const float4*)&ae2_w[e4];
        uint2 o;
        ((__half2*)&o)[0] = __floats2half2_rn(v.x, v.y);
        ((__half2*)&o)[1] = __floats2half2_rn(v.z, v.w);
        *(uint2*)&g_wae2[e4] = o;
    } else if (u < U_M1) {
        int e4 = (u - U_AE2) << 2;
        float4 v = *(const float4*)&m1_w[e4];
        uint2 o;
        ((__half2*)&o)[0] = __floats2half2_rn(v.x, v.y);
        ((__half2*)&o)[1] = __floats2half2_rn(v.z, v.w);
        *(uint2*)&g_wm1[e4] = o;
    } else if (u < U_M2) {
        int e4 = (u - U_M1) << 2;
        float4 v = *(const float4*)&m2_w[e4];
        uint2 o;
        ((__half2*)&o)[0] = __floats2half2_rn(v.x, v.y);
        ((__half2*)&o)[1] = __floats2half2_rn(v.z, v.w);
        *(uint2*)&g_wm2[e4] = o;
    } else if (u < U_MOD) {
        int r = u - U_M2;
        int k = r >> 8, j4 = (r & 255) << 2;
        float4 sh = *(const float4*)&mod_w[(size_t)k * 4096 + j4];
        float4 sc = *(const float4*)&mod_w[(size_t)k * 4096 + 1024 + j4];
        uint4 o;
        ((__half2*)&o)[0] = __floats2half2_rn(sh.x, sc.x);
        ((__half2*)&o)[1] = __floats2half2_rn(sh.y, sc.y);
        ((__half2*)&o)[2] = __floats2half2_rn(sh.z, sc.z);
        ((__half2*)&o)[3] = __floats2half2_rn(sh.w, sc.w);
        *(uint4*)&g_wmod[(size_t)k * 2048 + 2 * j4] = o;
    } else {
        int r = u - U_MOD;
        int i = r << 2;
        float4 v;
        if (i < 1024)      v = *(const float4*)&q_b[i];
        else if (i < 2048) v = *(const float4*)&k_b[i - 1024];
        else               v = *(const float4*)&v_b[i - 2048];
        *(float4*)&g_bqkv[i] = v;
    }
}

// ---------------- rmsnorm ------------------------------------------------------------
__global__ void rmsnorm_kernel(const float* __restrict__ x,
                               const float* __restrict__ w,
                               __half* __restrict__ y)
{
    int row = blockIdx.x;
    const float* xr = x + (size_t)row * DIMD;
    float v[4];
    float s = 0.f;
#pragma unroll
    for (int i = 0; i < 4; i++) {
        v[i] = xr[threadIdx.x + i * 256];
        s += v[i] * v[i];
    }
#pragma unroll
    for (int o = 16; o > 0; o >>= 1) s += __shfl_xor_sync(0xffffffffu, s, o);
    __shared__ float red[8];
    if ((threadIdx.x & 31) == 0) red[threadIdx.x >> 5] = s;
    __syncthreads();
    if (threadIdx.x == 0) {
        float t = 0.f;
#pragma unroll
        for (int i = 0; i < 8; i++) t += red[i];
        red[0] = rsqrtf(t * (1.0f / DIMD) + 1e-6f);
    }
    __syncthreads();
    float r = red[0];
    __half* yr = y + (size_t)row * DIMD;
#pragma unroll
    for (int i = 0; i < 4; i++) {
        int c = threadIdx.x + i * 256;
        yr[c] = __float2half_rn(v[i] * r * w[c]);
    }
}

// ---------------- per-head rmsnorm on qkv buffer --------------------------------------
__global__ void headnorm_kernel(__half* __restrict__ qkv,
                                const float* __restrict__ qw, const float* __restrict__ kw)
{
    int sel = blockIdx.y;
    const float* w = sel ? kw : qw;
    float scale = sel ? 1.0f : 0.125f;
    int gw   = (blockIdx.x * blockDim.x + threadIdx.x) >> 5;
    int lane = threadIdx.x & 31;
    if (gw >= BT * NH) return;
    int token = gw >> 4, head = gw & 15;
    __half* p = qkv + (size_t)token * QSTR + sel * 1024 + head * 64;
    float a = __half2float(p[lane]);
    float b = __half2float(p[lane + 32]);
    float s = a * a + b * b;
#pragma unroll
    for (int o = 16; o > 0; o >>= 1) s += __shfl_xor_sync(0xffffffffu, s, o);
    float r = rsqrtf(s * (1.0f / HD) + 1e-6f) * scale;
    p[lane]      = __float2half_rn(a * r * w[lane]);
    p[lane + 32] = __float2half_rn(b * r * w[lane + 32]);
}

// ---------------- ae1 (K=16) -----------------------------------------------------------
__global__ void __launch_bounds__(256) ae1_kernel(
    const float* __restrict__ A, const float* __restrict__ W,
    const float* __restrict__ bias, __half* __restrict__ C)
{
    __shared__ float Ws[16 * 256];
    __shared__ float As[32 * 16];
    int tid = threadIdx.x;
    int colbase = blockIdx.y * 256;
    for (int i = tid; i < 1024; i += 256) {
        int row = i >> 6, c4 = (i & 63) << 2;
        *(float4*)&Ws[row * 256 + c4] = *(const float4*)&W[(size_t)row * 1024 + colbase + c4];
    }
    int brow = blockIdx.x * 32;
    if (tid < 128)
        ((float4*)As)[tid] = ((const float4*)(A + (size_t)brow * 16))[tid];
    __syncthreads();

    int r = tid >> 3, lane8 = tid & 7;
    float a[16];
#pragma unroll
    for (int kk = 0; kk < 16; kk++) a[kk] = As[r * 16 + kk];
    __half* Cr = C + (size_t)(brow + r) * 1024 + colbase;

#pragma unroll
    for (int j = 0; j < 8; j++) {
        int col = lane8 * 4 + j * 32;
        float4 o = make_float4(bias[colbase + col],     bias[colbase + col + 1],
                               bias[colbase + col + 2], bias[colbase + col + 3]);
#pragma unroll
        for (int kk = 0; kk < 16; kk++) {
            float4 wv = *(float4*)&Ws[kk * 256 + col];
            o.x += a[kk] * wv.x; o.y += a[kk] * wv.y;
            o.z += a[kk] * wv.z; o.w += a[kk] * wv.w;
        }
        o.x = o.x / (1.f + expf(-o.x));
        o.y = o.y / (1.f + expf(-o.y));
        o.z = o.z / (1.f + expf(-o.z));
        o.w = o.w / (1.f + expf(-o.w));
        *(__half2*)&Cr[col]     = __floats2half2_rn(o.x, o.y);
        *(__half2*)&Cr[col + 2] = __floats2half2_rn(o.z, o.w);
    }
}

// ============ fp16 GEMM 128x128x64, 3-stage, natural-layout B (round-14) ============
#define EPI_NONE 0
#define EPI_SILU 1
#define EPI_GELU 2
#define EPI_RES  3
#define EPI_MOD  4

#define GBK 64
#define GSTR 72
#define BSTR 136
#define APS  (128 * GSTR)
#define BPS  (64 * BSTR)
#define HMMA_SMEM (3 * (APS + BPS) * 2)

__device__ __forceinline__ void cp16h(__half* s, const __half* g)
{
    uint32_t sa = (uint32_t)__cvta_generic_to_shared(s);
    asm volatile("cp.async.cg.shared.global [%0], [%1], 16;\n" :: "r"(sa), "l"(g));
}

__device__ __forceinline__ void mma_f16(float* c, const uint32_t* a, const uint32_t* b)
{
    asm volatile(
        "mma.sync.aligned.m16n8k16.row.col.f32.f16.f16.f32 "
        "{%0,%1,%2,%3},{%4,%5,%6,%7},{%8,%9},{%0,%1,%2,%3};"
        : "+f"(c[0]), "+f"(c[1]), "+f"(c[2]), "+f"(c[3])
        : "r"(a[0]), "r"(a[1]), "r"(a[2]), "r"(a[3]), "r"(b[0]), "r"(b[1]));
}

__device__ __forceinline__ void ldm_x4(uint32_t* r, const __half* p)
{
    uint32_t addr = (uint32_t)__cvta_generic_to_shared(p);
    asm volatile("ldmatrix.sync.aligned.m8n8.x4.shared.b16 {%0,%1,%2,%3}, [%4];"
                 : "=r"(r[0]), "=r"(r[1]), "=r"(r[2]), "=r"(r[3]) : "r"(addr));
}

__device__ __forceinline__ void ldm_x4t(uint32_t* r, const __half* p)
{
    uint32_t addr = (uint32_t)__cvta_generic_to_shared(p);
    asm volatile("ldmatrix.sync.aligned.m8n8.x4.trans.shared.b16 {%0,%1,%2,%3}, [%4];"
                 : "=r"(r[0]), "=r"(r[1]), "=r"(r[2]), "=r"(r[3]) : "r"(addr));
}

template<int EPI, int HOUT>
__global__ void __launch_bounds__(256, 2) hmma_kernel(
    const __half* __restrict__ A, const __half* __restrict__ Wn,
    const float* __restrict__ bias, const float* __restrict__ Res,
    void* __restrict__ Cv, int M, int N, int K)
{
    extern __shared__ __half hsm[];
    __half* Asm = hsm;
    __half* Bsm = hsm + 3 * APS;

    int tid  = threadIdx.x;
    int brow = blockIdx.y * 128;
    int bcol = blockIdx.x * 128;
    int warp = tid >> 5, lane = tid & 31;
    int g = lane >> 2, t = lane & 3;
    int wr = warp & 1, wc = warp >> 1;

    int ar = tid >> 3, ac = (tid & 7) << 3;
    const __half* Agb = A + (size_t)(brow + ar) * K + ac;
    int br = tid >> 4, bc = (tid & 15) << 3;
    const __half* Bgb = Wn + (size_t)br * N + bcol + bc;

    int a_row  = wr * 64 + (lane & 15);
    int a_koff = (lane >> 4) << 3;

    float acc[4][4][4];
#pragma unroll
    for (int i = 0; i < 4; i++)
#pragma unroll
        for (int j = 0; j < 4; j++)
#pragma unroll
            for (int c = 0; c < 4; c++) acc[i][j][c] = 0.f;

    int nk = K / GBK;

#pragma unroll
    for (int s = 0; s < 2; s++) {
        int kc = s * GBK;
#pragma unroll
        for (int p = 0; p < 4; p++)
            cp16h(&Asm[s * APS + (ar + 32 * p) * GSTR + ac], Agb + (size_t)32 * p * K + kc);
#pragma unroll
        for (int p = 0; p < 4; p++)
            cp16h(&Bsm[s * BPS + (br + 16 * p) * BSTR + bc], Bgb + (size_t)(kc + 16 * p) * N);
        asm volatile("cp.async.commit_group;");
    }

    int st = 0;
    for (int i = 0; i < nk; i++) {
        asm volatile("cp.async.wait_group 1;" ::: "memory");
        __syncthreads();

        if (i + 2 < nk) {
            int kc = (i + 2) * GBK;
            int s2 = st + 2; if (s2 >= 3) s2 -= 3;
#pragma unroll
            for (int p = 0; p < 4; p++)
                cp16h(&Asm[s2 * APS + (ar + 32 * p) * GSTR + ac], Agb + (size_t)32 * p * K + kc);
#pragma unroll
            for (int p = 0; p < 4; p++)
                cp16h(&Bsm[s2 * BPS + (br + 16 * p) * BSTR + bc], Bgb + (size_t)(kc + 16 * p) * N);
        }
        asm volatile("cp.async.commit_group;");

        const __half* Sb = &Asm[st * APS];
        const __half* Tb = &Bsm[st * BPS];
#pragma unroll
        for (int kp2 = 0; kp2 < 2; kp2++) {
            int k0 = kp2 * 32;
            uint32_t af[2][4][4];
#pragma unroll
            for (int ti = 0; ti < 4; ti++) {
                ldm_x4(af[0][ti], Sb + (a_row + ti * 16) * GSTR + k0 + a_koff);
                ldm_x4(af[1][ti], Sb + (a_row + ti * 16) * GSTR + k0 + 16 + a_koff);
            }
#pragma unroll
            for (int tj = 0; tj < 4; tj++) {
                uint32_t vb[4];
                ldm_x4t(vb, Tb + (size_t)(k0 + lane) * BSTR + wc * 32 + tj * 8);
#pragma unroll
                for (int ti = 0; ti < 4; ti++) {
                    mma_f16(acc[ti][tj], af[0][ti], vb);
                    mma_f16(acc[ti][tj], af[1][ti], vb + 2);
                }
            }
        }
        if (++st == 3) st = 0;
    }

#pragma unroll
    for (int ti = 0; ti < 4; ti++) {
        int r0 = brow + wr * 64 + ti * 16 + g;
#pragma unroll
        for (int tj = 0; tj < 4; tj++) {
            int c0 = bcol + wc * 32 + tj * 8 + 2 * t;
#pragma unroll
            for (int half_i = 0; half_i < 2; half_i++) {
                int row = r0 + half_i * 8;
                float vx = acc[ti][tj][half_i * 2 + 0];
                float vy = acc[ti][tj][half_i * 2 + 1];
                if (EPI == EPI_MOD) {
                    int j = c0 >> 1;
                    float shift = vx + bias[j];
                    float scale = vy + bias[1024 + j];
                    float res = Res[(size_t)row * (N >> 1) + j];
                    ((float*)Cv)[(size_t)row * (N >> 1) + j] = res * (1.f + scale) + shift;
                    continue;
                }
                vx += bias[c0]; vy += bias[c0 + 1];
                if (EPI == EPI_SILU) {
                    vx = vx / (1.f + expf(-vx));
                    vy = vy / (1.f + expf(-vy));
                } else if (EPI == EPI_GELU) {
                    const float cst = 0.70710678118654752f;
                    vx = 0.5f * vx * (1.f + erff(vx * cst));
                    vy = 0.5f * vy * (1.f + erff(vy * cst));
                } else if (EPI == EPI_RES) {
                    float2 rv = *(const float2*)&Res[(size_t)row * N + c0];
                    vx += rv.x; vy += rv.y;
                }
                if (HOUT) {
                    *(__half2*)((__half*)Cv + (size_t)row * N + c0) = __floats2half2_rn(vx, vy);
                } else {
                    *(float2*)((float*)Cv + (size_t)row * N + c0) = make_float2(vx, vy);
                }
            }
        }
    }
}

// ---------------- fp16 flash attention, 128x64 tiles (unchanged) --------------------
#define AST 72
#define ATT_SMEM ((128 * AST + 4 * 64 * AST) * 2)

__global__ void __launch_bounds__(256) attn_mma_kernel(
    const __half* __restrict__ QKV, __half* __restrict__ O)
{
    extern __shared__ __half asm_[];
    __half* Qs = asm_;
    __half* Ks = Qs + 128 * AST;
    __half* Vs = Ks + 2 * 64 * AST;
    __half* Ps = Qs;

    int tid = threadIdx.x, warp = tid >> 5, lane = tid & 31;
    int g = lane >> 2, t = lane & 3;
    int qt = (TT / 128 - 1) - blockIdx.x;
    int bh = blockIdx.y, b = bh >> 4, h = bh & 15;

    const __half* Qg = QKV + (size_t)b * TT * QSTR + (size_t)h * HD;
    const __half* Kg = Qg + 1024;
    const __half* Vg = Qg + 2048;

    {
        int lrow = tid >> 1, ld32 = (tid & 1) << 5;
        const __half* src = Qg + (size_t)(qt * 128 + lrow) * QSTR + ld32;
        __half* dst = Qs + lrow * AST + ld32;
        *(uint4*)(dst)      = *(const uint4*)(src);
        *(uint4*)(dst + 8)  = *(const uint4*)(src + 8);
        *(uint4*)(dst + 16) = *(const uint4*)(src + 16);
        *(uint4*)(dst + 24) = *(const uint4*)(src + 24);
    }
    int lrow = tid >> 2, ld16 = (tid & 3) << 4;
    {
        const __half* kp = Kg + (size_t)lrow * QSTR + ld16;
        const __half* vp = Vg + (size_t)lrow * QSTR + ld16;
        cp16h(&Ks[lrow * AST + ld16],     kp);
        cp16h(&Ks[lrow * AST + ld16 + 8], kp + 8);
        cp16h(&Vs[lrow * AST + ld16],     vp);
        cp16h(&Vs[lrow * AST + ld16 + 8], vp + 8);
        asm volatile("cp.async.commit_group;");
    }
    __syncthreads();

    int r0 = warp * 16 + g;
    uint32_t qf[4][4];
#pragma unroll
    for (int ks = 0; ks < 4; ks++) {
        int k0 = ks * 16;
        qf[ks][0] = *(const uint32_t*)&Qs[(r0)     * AST + k0 + 2 * t];
        qf[ks][1] = *(const uint32_t*)&Qs[(r0 + 8) * AST + k0 + 2 * t];
        qf[ks][2] = *(const uint32_t*)&Qs[(r0)     * AST + k0 + 2 * t + 8];
        qf[ks][3] = *(const uint32_t*)&Qs[(r0 + 8) * AST + k0 + 2 * t + 8];
    }
    __half* Pw = Ps + warp * 16 * AST;

    int kb_row  = ((lane >> 4) << 3) + (lane & 7);
    int kb_koff = ((lane >> 3) & 1) << 3;
    int vb_row  = lane;

    float m0 = -1e30f, m1 = -1e30f, l0 = 0.f, l1 = 0.f;
    float acc[8][4];
#pragma unroll
    for (int tj = 0; tj < 8; tj++)
#pragma unroll
        for (int c = 0; c < 4; c++) acc[tj][c] = 0.f;

    int nkt = 2 * qt + 2;
    for (int kt = 0; kt < nkt; kt++) {
        int cur = kt & 1;
        asm volatile("cp.async.wait_group 0;" ::: "memory");
        __syncthreads();

        if (kt + 1 < nkt) {
            int nxt = cur ^ 1;
            const __half* kp = Kg + (size_t)((kt + 1) * 64 + lrow) * QSTR + ld16;
            const __half* vp = Vg + (size_t)((kt + 1) * 64 + lrow) * QSTR + ld16;
            cp16h(&Ks[nxt * 64 * AST + lrow * AST + ld16],     kp);
            cp16h(&Ks[nxt * 64 * AST + lrow * AST + ld16 + 8], kp + 8);
            cp16h(&Vs[nxt * 64 * AST + lrow * AST + ld16],     vp);
            cp16h(&Vs[nxt * 64 * AST + lrow * AST + ld16 + 8], vp + 8);
        }
        asm volatile("cp.async.commit_group;");

        const __half* Kc = Ks + cur * 64 * AST;
        const __half* Vc = Vs + cur * 64 * AST;

        float s[8][4];
#pragma unroll
        for (int tj = 0; tj < 8; tj++)
#pragma unroll
            for (int c = 0; c < 4; c++) s[tj][c] = 0.f;
#pragma unroll
        for (int ks = 0; ks < 4; ks++) {
            int k0 = ks * 16;
#pragma unroll
            for (int tp = 0; tp < 4; tp++) {
                uint32_t bf4[4];
                ldm_x4(bf4, Kc + (tp * 16 + kb_row) * AST + k0 + kb_koff);
                mma_f16(s[2 * tp],     qf[ks], bf4);
                mma_f16(s[2 * tp + 1], qf[ks], bf4 + 2);
            }
        }

        if (kt >= 2 * qt) {
            int cgb = kt * 64;
            int rg0 = qt * 128 + r0, rg1 = rg0 + 8;
#pragma unroll
            for (int tj = 0; tj < 8; tj++) {
                int c0 = cgb + tj * 8 + 2 * t;
                if (c0     > rg0) s[tj][0] = -1e30f;
                if (c0 + 1 > rg0) s[tj][1] = -1e30f;
                if (c0     > rg1) s[tj][2] = -1e30f;
                if (c0 + 1 > rg1) s[tj][3] = -1e30f;
            }
        }

        float rm0 = -1e30f, rm1 = -1e30f;
#pragma unroll
        for (int tj = 0; tj < 8; tj++) {
            rm0 = fmaxf(rm0, fmaxf(s[tj][0], s[tj][1]));
            rm1 = fmaxf(rm1, fmaxf(s[tj][2], s[tj][3]));
        }
#pragma unroll
        for (int o = 1; o < 4; o <<= 1) {
            rm0 = fmaxf(rm0, __shfl_xor_sync(0xffffffffu, rm0, o));
            rm1 = fmaxf(rm1, __shfl_xor_sync(0xffffffffu, rm1, o));
        }
        float nm0 = fmaxf(m0, rm0), nm1 = fmaxf(m1, rm1);
        float a0 = __expf(m0 - nm0), a1 = __expf(m1 - nm1);
        m0 = nm0; m1 = nm1;

        float ls0 = 0.f, ls1 = 0.f;
#pragma unroll
        for (int tj = 0; tj < 8; tj++) {
            s[tj][0] = __expf(s[tj][0] - nm0);
            s[tj][1] = __expf(s[tj][1] - nm0);
            s[tj][2] = __expf(s[tj][2] - nm1);
            s[tj][3] = __expf(s[tj][3] - nm1);
            ls0 += s[tj][0] + s[tj][1];
            ls1 += s[tj][2] + s[tj][3];
        }
#pragma unroll
        for (int o = 1; o < 4; o <<= 1) {
            ls0 += __shfl_xor_sync(0xffffffffu, ls0, o);
            ls1 += __shfl_xor_sync(0xffffffffu, ls1, o);
        }
        l0 = l0 * a0 + ls0;
        l1 = l1 * a1 + ls1;

#pragma unroll
        for (int tj = 0; tj < 8; tj++) {
            int c0 = tj * 8 + 2 * t;
            *(__half2*)&Pw[(g)     * AST + c0] = __floats2half2_rn(s[tj][0], s[tj][1]);
            *(__half2*)&Pw[(g + 8) * AST + c0] = __floats2half2_rn(s[tj][2], s[tj][3]);
        }
        __syncwarp();

#pragma unroll
        for (int tj = 0; tj < 8; tj++) {
            acc[tj][0] *= a0; acc[tj][1] *= a0;
            acc[tj][2] *= a1; acc[tj][3] *= a1;
        }

#pragma unroll
        for (int kp2 = 0; kp2 < 2; kp2++) {
            int k0 = kp2 * 32;
            uint32_t pf0[4], pf1[4];
            pf0[0] = *(const uint32_t*)&Pw[(g)     * AST + k0 + 2 * t];
            pf0[1] = *(const uint32_t*)&Pw[(g + 8) * AST + k0 + 2 * t];
            pf0[2] = *(const uint32_t*)&Pw[(g)     * AST + k0 + 2 * t + 8];
            pf0[3] = *(const uint32_t*)&Pw[(g + 8) * AST + k0 + 2 * t + 8];
            pf1[0] = *(const uint32_t*)&Pw[(g)     * AST + k0 + 16 + 2 * t];
            pf1[1] = *(const uint32_t*)&Pw[(g + 8) * AST + k0 + 16 + 2 * t];
            pf1[2] = *(const uint32_t*)&Pw[(g)     * AST + k0 + 16 + 2 * t + 8];
            pf1[3] = *(const uint32_t*)&Pw[(g + 8) * AST + k0 + 16 + 2 * t + 8];
#pragma unroll
            for (int tj = 0; tj < 8; tj++) {
                uint32_t vb[4];
                ldm_x4t(vb, Vc + (k0 + vb_row) * AST + tj * 8);
                mma_f16(acc[tj], pf0, vb);
                mma_f16(acc[tj], pf1, vb + 2);
            }
        }
    }

    float inv0 = 1.f / l0, inv1 = 1.f / l1;
    __half* Og = O + (size_t)b * TT * DIMD + (size_t)(qt * 128) * DIMD + (size_t)h * HD;
#pragma unroll
    for (int tj = 0; tj < 8; tj++) {
        int c0 = tj * 8 + 2 * t;
        *(__half2*)&Og[(size_t)(r0)     * DIMD + c0] = __floats2half2_rn(acc[tj][0] * inv0, acc[tj][1] * inv0);
        *(__half2*)&Og[(size_t)(r0 + 8) * DIMD + c0] = __floats2half2_rn(acc[tj][2] * inv1, acc[tj][3] * inv1);
    }
}

// ------------------------------- launch --------------------------------------------
extern "C" void kernel_launch(void* const* d_in, const int* in_sizes, int n_in,
                              void* d_out, int out_size)
{
    const float* x       = (const float*)d_in[0];
    const float* actions = (const float*)d_in[1];
    const float* n1_w    = (const float*)d_in[2];
    const float* n2_w    = (const float*)d_in[3];
    const float* q_w     = (const float*)d_in[4];
    const float* q_b     = (const float*)d_in[5];
    const float* k_w     = (const float*)d_in[6];
    const float* k_b     = (const float*)d_in[7];
    const float* v_w     = (const float*)d_in[8];
    const float* v_b     = (const float*)d_in[9];
    const float* qn_w    = (const float*)d_in[10];
    const float* kn_w    = (const float*)d_in[11];
    const float* o_w     = (const float*)d_in[12];
    const float* o_b     = (const float*)d_in[13];
    const float* ae1_w   = (const float*)d_in[14];
    const float* ae1_b   = (const float*)d_in[15];
    const float* ae2_w   = (const float*)d_in[16];
    const float* ae2_b   = (const float*)d_in[17];
    const float* mod_w   = (const float*)d_in[18];
    const float* mod_b   = (const float*)d_in[19];
    const float* m1_w    = (const float*)d_in[20];
    const float* m1_b    = (const float*)d_in[21];
    const float* m2_w    = (const float*)d_in[22];
    const float* m2_b    = (const float*)d_in[23];
    float* out           = (float*)d_out;

    __half *h, *a1, *qkv, *ao, *ae, *hid;
    float *x1, *bqkv;
    __half *wqkv, *wo, *wae2, *wmod, *wm1, *wm2;
    cudaGetSymbolAddress((void**)&h,    g_h);
    cudaGetSymbolAddress((void**)&a1,   g_a1);
    cudaGetSymbolAddress((void**)&qkv,  g_qkv);
    cudaGetSymbolAddress((void**)&ao,   g_ao);
    cudaGetSymbolAddress((void**)&ae,   g_ae);
    cudaGetSymbolAddress((void**)&hid,  g_hid);
    cudaGetSymbolAddress((void**)&x1,   g_x1);
    cudaGetSymbolAddress((void**)&bqkv, g_bqkv);
    cudaGetSymbolAddress((void**)&wqkv, g_wqkv);
    cudaGetSymbolAddress((void**)&wo,   g_wo);
    cudaGetSymbolAddress((void**)&wae2, g_wae2);
    cudaGetSymbolAddress((void**)&wmod, g_wmod);
    cudaGetSymbolAddress((void**)&wm1,  g_wm1);
    cudaGetSymbolAddress((void**)&wm2,  g_wm2);

    static int init_done = 0;
    static cudaStream_t s1, s2;
    static cudaEvent_t evRoot, evConv, evH, evAe;
    if (!init_done) {
        cudaFuncSetAttribute((const void*)hmma_kernel<EPI_NONE, 1>, cudaFuncAttributeMaxDynamicSharedMemorySize, HMMA_SMEM);
        cudaFuncSetAttribute((const void*)hmma_kernel<EPI_SILU, 1>, cudaFuncAttributeMaxDynamicSharedMemorySize, HMMA_SMEM);
        cudaFuncSetAttribute((const void*)hmma_kernel<EPI_GELU, 1>, cudaFuncAttributeMaxDynamicSharedMemorySize, HMMA_SMEM);
        cudaFuncSetAttribute((const void*)hmma_kernel<EPI_RES,  0>, cudaFuncAttributeMaxDynamicSharedMemorySize, HMMA_SMEM);
        cudaFuncSetAttribute((const void*)hmma_kernel<EPI_MOD,  0>, cudaFuncAttributeMaxDynamicSharedMemorySize, HMMA_SMEM);
        cudaFuncSetAttribute((const void*)attn_mma_kernel, cudaFuncAttributeMaxDynamicSharedMemorySize, ATT_SMEM);
        cudaStreamCreateWithFlags(&s1, cudaStreamNonBlocking);
        cudaStreamCreateWithFlags(&s2, cudaStreamNonBlocking);
        cudaEventCreateWithFlags(&evRoot, cudaEventDisableTiming);
        cudaEventCreateWithFlags(&evConv, cudaEventDisableTiming);
        cudaEventCreateWithFlags(&evH,    cudaEventDisableTiming);
        cudaEventCreateWithFlags(&evAe,   cudaEventDisableTiming);
        init_done = 1;
    }

    dim3 g1024(8, 32);
    dim3 g2048(16, 32);
    dim3 g3072(24, 32);
    dim3 g4096(32, 32);

    // ---- fork (round-14 schedule) ----
    cudaEventRecord(evRoot, 0);
    cudaStreamWaitEvent(s1, evRoot, 0);
    cudaStreamWaitEvent(s2, evRoot, 0);

    ae1_kernel<<<dim3(BT / 32, 4), 256, 0, s1>>>(actions, ae1_w, ae1_b, a1);
    rmsnorm_kernel<<<BT, 256, 0, s2>>>(x, n1_w, h);
    cudaEventRecord(evH, s2);
    conv_all_kernel<<<U_TOT / 256, 256>>>(q_w, k_w, v_w, o_w, ae2_w, mod_w, m1_w, m2_w,
                                          q_b, k_b, v_b);
    cudaEventRecord(evConv, 0);

    cudaStreamWaitEvent(s1, evConv, 0);
    hmma_kernel<EPI_SILU, 1><<<g1024, 256, HMMA_SMEM, s1>>>(a1, wae2, ae2_b, nullptr, ae, BT, DIMD, DIMD);
    cudaEventRecord(evAe, s1);

    cudaStreamWaitEvent(0, evH, 0);
    hmma_kernel<EPI_NONE, 1><<<g3072, 256, HMMA_SMEM>>>(h, wqkv, bqkv, nullptr, qkv, BT, QSTR, DIMD);
    headnorm_kernel<<<dim3((BT * NH) / 8, 2), 256>>>(qkv, qn_w, kn_w);
    attn_mma_kernel<<<dim3(TT / 128, 2 * NH), 256, ATT_SMEM>>>(qkv, ao);
    hmma_kernel<EPI_RES, 0><<<g1024, 256, HMMA_SMEM>>>(ao, wo, o_b, x, x1, BT, DIMD, DIMD);

    cudaStreamWaitEvent(0, evAe, 0);
    hmma_kernel<EPI_MOD, 0><<<g2048, 256, HMMA_SMEM>>>(ae, wmod, mod_b, x1, x1, BT, 2048, DIMD);
    rmsnorm_kernel<<<BT, 256>>>(x1, n2_w, h);
    hmma_kernel<EPI_GELU, 1><<<g4096, 256, HMMA_SMEM>>>(h, wm1, m1_b, nullptr, hid, BT, MLPH, DIMD);
    hmma_kernel<EPI_RES, 0><<<g1024, 256, HMMA_SMEM>>>(hid, wm2, m2_b, x1, out, BT, DIMD, MLPH);
}